// round 10
// baseline (speedup 1.0000x reference)
#include <cuda_runtime.h>
#include <cuda_bf16.h>
#include <cstdint>

#define NNODES 50000
#define NEDGES 800000
#define NGRAPHS 512
#define HID 128
#define NCLS 10
#define SCAN_B ((NNODES + 255) / 256)   // 196 scan blocks

// ---------------- scratch (device globals; no allocs allowed) ----------------
__device__ float g_deg_in[NNODES];
__device__ float g_deg_out[NNODES];
__device__ float g_norm_src[NNODES];
__device__ float g_norm_dst[NNODES];
__device__ float g_ha[(size_t)NNODES * HID];
__device__ float g_hb[(size_t)NNODES * HID];
__device__ float g_aggA[(size_t)NNODES * HID];
__device__ float g_aggB[(size_t)NNODES * HID];
__device__ float g_hg[NGRAPHS * HID];
__device__ float g_cnt[NGRAPHS];
// CSR by destination
__device__ int g_off[NNODES + 1];
__device__ int g_cursor[NNODES];
__device__ int g_eidx[NEDGES];
__device__ int g_bsum[SCAN_B];
__device__ int g_boff[SCAN_B];

__device__ __forceinline__ void red_add_v4(float* addr, float4 v) {
    asm volatile("red.global.add.v4.f32 [%0], {%1,%2,%3,%4};"
                 :: "l"(addr), "f"(v.x), "f"(v.y), "f"(v.z), "f"(v.w) : "memory");
}

__device__ __forceinline__ uint32_t f32_to_tf32(float v) {
    uint32_t r;
    asm("cvt.rna.tf32.f32 %0, %1;" : "=r"(r) : "f"(v));
    return r;
}

__device__ __forceinline__ void mma_tf32(float d[4], const uint32_t a[4],
                                         uint32_t b0, uint32_t b1) {
    asm volatile("mma.sync.aligned.m16n8k8.row.col.f32.tf32.tf32.f32 "
                 "{%0,%1,%2,%3}, {%4,%5,%6,%7}, {%8,%9}, {%0,%1,%2,%3};"
                 : "+f"(d[0]), "+f"(d[1]), "+f"(d[2]), "+f"(d[3])
                 : "r"(a[0]), "r"(a[1]), "r"(a[2]), "r"(a[3]), "r"(b0), "r"(b1));
}

// ---------------- zero all accumulated state ----------------
__global__ __launch_bounds__(256) void zero_kernel() {
    int i = blockIdx.x * blockDim.x + threadIdx.x;     // 0..65535
    if (i < NNODES) { g_deg_in[i] = 0.f; g_deg_out[i] = 0.f; g_cursor[i] = 0; }
    if (i < NGRAPHS * HID) g_hg[i] = 0.f;
    if (i < NGRAPHS) g_cnt[i] = 0.f;
}

// ---------------- degree histograms ----------------
__global__ __launch_bounds__(256) void degree_kernel(const int* __restrict__ src,
                                                     const int* __restrict__ dst) {
    int e = blockIdx.x * blockDim.x + threadIdx.x;
    if (e < NEDGES) {
        atomicAdd(&g_deg_out[src[e]], 1.0f);
        atomicAdd(&g_deg_in[dst[e]], 1.0f);
    }
}

// ---------------- norms ----------------
__global__ __launch_bounds__(256) void norm_kernel() {
    int i = blockIdx.x * blockDim.x + threadIdx.x;
    if (i < NNODES) {
        g_norm_src[i] = rsqrtf(fmaxf(g_deg_out[i], 1.0f));
        g_norm_dst[i] = rsqrtf(fmaxf(g_deg_in[i], 1.0f));
    }
}

// ---------------- scan stage A: per-block exclusive scan + block sums ---------
__global__ __launch_bounds__(256) void scan_a_kernel() {
    __shared__ int wsum[8];
    int t = threadIdx.x, lane = t & 31, wid = t >> 5;
    int i = blockIdx.x * 256 + t;
    int v = (i < NNODES) ? (int)g_deg_in[i] : 0;
    int x = v;
#pragma unroll
    for (int o = 1; o < 32; o <<= 1) { int y = __shfl_up_sync(~0u, x, o); if (lane >= o) x += y; }
    if (lane == 31) wsum[wid] = x;
    __syncthreads();
    if (wid == 0 && lane < 8) {
        int w = wsum[lane];
#pragma unroll
        for (int o = 1; o < 8; o <<= 1) { int y = __shfl_up_sync(0xffu, w, o); if (lane >= o) w += y; }
        wsum[lane] = w;
    }
    __syncthreads();
    int incl = x + (wid ? wsum[wid - 1] : 0);
    if (i < NNODES) g_off[i] = incl - v;
    if (t == 255) g_bsum[blockIdx.x] = incl;
}

// ---------------- scan stage B: scan the block sums (1 block) ----------------
__global__ __launch_bounds__(256) void scan_b_kernel() {
    __shared__ int wsum[8];
    int t = threadIdx.x, lane = t & 31, wid = t >> 5;
    int v = (t < SCAN_B) ? g_bsum[t] : 0;
    int x = v;
#pragma unroll
    for (int o = 1; o < 32; o <<= 1) { int y = __shfl_up_sync(~0u, x, o); if (lane >= o) x += y; }
    if (lane == 31) wsum[wid] = x;
    __syncthreads();
    if (wid == 0 && lane < 8) {
        int w = wsum[lane];
#pragma unroll
        for (int o = 1; o < 8; o <<= 1) { int y = __shfl_up_sync(0xffu, w, o); if (lane >= o) w += y; }
        wsum[lane] = w;
    }
    __syncthreads();
    int incl = x + (wid ? wsum[wid - 1] : 0);
    if (t < SCAN_B) g_boff[t] = incl - v;
    if (t == SCAN_B - 1) g_off[NNODES] = incl;
}

// ---------------- scan stage C: add block offsets ----------------
__global__ __launch_bounds__(256) void scan_c_kernel() {
    int i = blockIdx.x * 256 + threadIdx.x;
    if (i < NNODES && blockIdx.x > 0) g_off[i] += g_boff[blockIdx.x];
}

// ---------------- CSR fill: slot per edge under its dst ----------------
__global__ __launch_bounds__(256) void fill_kernel(const int* __restrict__ src,
                                                   const int* __restrict__ dst) {
    int e = blockIdx.x * blockDim.x + threadIdx.x;
    if (e < NEDGES) {
        int d = dst[e];
        int p = atomicAdd(&g_cursor[d], 1);
        g_eidx[g_off[d] + p] = src[e];
    }
}

// ---------------- layer 0: gather scalar + dense, fused; one warp per node ----
__global__ __launch_bounds__(256) void gather0_dense_kernel(const float* __restrict__ W0,
                                                            const float* __restrict__ b0) {
    int node = (blockIdx.x * blockDim.x + threadIdx.x) >> 5;
    int lane = threadIdx.x & 31;
    if (node >= NNODES) return;
    int beg = g_off[node], end = g_off[node + 1];
    float a = 0.f;
    for (int j = beg + lane; j < end; j += 32) {
        int s = g_eidx[j];
        a += g_deg_in[s] * g_norm_src[s];
    }
#pragma unroll
    for (int o = 16; o; o >>= 1) a += __shfl_xor_sync(~0u, a, o);
    a *= g_norm_dst[node];
    float ns = g_norm_src[node];
    float4 w = __ldg(&((const float4*)W0)[lane]);
    float4 b = __ldg(&((const float4*)b0)[lane]);
    float4 r;
    r.x = fmaxf(a * w.x + b.x, 0.f) * ns;
    r.y = fmaxf(a * w.y + b.y, 0.f) * ns;
    r.z = fmaxf(a * w.z + b.z, 0.f) * ns;
    r.w = fmaxf(a * w.w + b.w, 0.f) * ns;
    ((float4*)(g_ha + (size_t)node * HID))[lane] = r;
}

// ---------------- CSR gather: one warp per node, 4-deep independent loads -----
template <int PHASE>
__global__ __launch_bounds__(256) void gather_kernel() {
    const float4* __restrict__ h = (const float4*)(PHASE == 0 ? g_ha : g_hb);
    float4* __restrict__ agg = (float4*)(PHASE == 0 ? g_aggA : g_aggB);
    int node = (blockIdx.x * blockDim.x + threadIdx.x) >> 5;
    int lane = threadIdx.x & 31;
    if (node >= NNODES) return;
    int beg = g_off[node], end = g_off[node + 1];
    float4 a0 = make_float4(0.f, 0.f, 0.f, 0.f);
    float4 a1 = make_float4(0.f, 0.f, 0.f, 0.f);
    float4 a2 = make_float4(0.f, 0.f, 0.f, 0.f);
    float4 a3 = make_float4(0.f, 0.f, 0.f, 0.f);
    for (int j = beg; j < end; j += 32) {
        int n = end - j;
        int myidx = (lane < n) ? __ldg(&g_eidx[j + lane]) : 0;
        int cnt = n < 32 ? n : 32;
        int k = 0;
        for (; k + 3 < cnt; k += 4) {
            int s0 = __shfl_sync(~0u, myidx, k);
            int s1 = __shfl_sync(~0u, myidx, k + 1);
            int s2 = __shfl_sync(~0u, myidx, k + 2);
            int s3 = __shfl_sync(~0u, myidx, k + 3);
            float4 v0 = __ldg(&h[(size_t)s0 * 32 + lane]);
            float4 v1 = __ldg(&h[(size_t)s1 * 32 + lane]);
            float4 v2 = __ldg(&h[(size_t)s2 * 32 + lane]);
            float4 v3 = __ldg(&h[(size_t)s3 * 32 + lane]);
            a0.x += v0.x; a0.y += v0.y; a0.z += v0.z; a0.w += v0.w;
            a1.x += v1.x; a1.y += v1.y; a1.z += v1.z; a1.w += v1.w;
            a2.x += v2.x; a2.y += v2.y; a2.z += v2.z; a2.w += v2.w;
            a3.x += v3.x; a3.y += v3.y; a3.z += v3.z; a3.w += v3.w;
        }
        for (; k < cnt; k++) {
            int s0 = __shfl_sync(~0u, myidx, k);
            float4 v0 = __ldg(&h[(size_t)s0 * 32 + lane]);
            a0.x += v0.x; a0.y += v0.y; a0.z += v0.z; a0.w += v0.w;
        }
    }
    a0.x += a1.x + a2.x + a3.x;
    a0.y += a1.y + a2.y + a3.y;
    a0.z += a1.z + a2.z + a3.z;
    a0.w += a1.w + a2.w + a3.w;
    agg[(size_t)node * 32 + lane] = a0;
}

// ---------------- GEMM via 3xTF32 mma.sync -------------------------------------
template <int PHASE>
__global__ __launch_bounds__(256) void gemm_tf32_kernel(const float* __restrict__ W,
                                                        const float* __restrict__ bias) {
    const float* __restrict__ A = (PHASE == 0) ? g_aggA : g_aggB;
    float* __restrict__ O = (PHASE == 0) ? g_hb : g_ha;

    __shared__ float As[64][36];
    __shared__ float Wh[32][136];
    __shared__ float Wl[32][136];

    int t = threadIdx.x;
    int w = t >> 5, lane = t & 31;
    int gid = lane >> 2, tig = lane & 3;
    int m_base = (w >> 1) * 16;
    int n_base = (w & 1) * 64;
    int row0 = blockIdx.x * 64;

    float d[8][4];
#pragma unroll
    for (int nt = 0; nt < 8; nt++)
#pragma unroll
        for (int i = 0; i < 4; i++) d[nt][i] = 0.f;

    for (int k0 = 0; k0 < HID; k0 += 32) {
#pragma unroll
        for (int i = 0; i < 16; i++) {
            int idx = t + i * 256;
            int r = idx >> 7, c = idx & 127;
            float v = W[(size_t)(k0 + r) * HID + c];
            uint32_t hb = f32_to_tf32(v);
            float hf = __uint_as_float(hb);
            uint32_t lb = f32_to_tf32(v - hf);
            Wh[r][c] = hf;
            Wl[r][c] = __uint_as_float(lb);
        }
#pragma unroll
        for (int i = 0; i < 8; i++) {
            int idx = t + i * 256;
            int r = idx >> 5, kk = idx & 31;
            int row = row0 + r;
            float v = 0.f;
            if (row < NNODES) v = A[(size_t)row * HID + k0 + kk] * g_norm_dst[row];
            As[r][kk] = v;
        }
        __syncthreads();

#pragma unroll
        for (int ks = 0; ks < 4; ks++) {
            uint32_t ah[4], al[4];
#pragma unroll
            for (int i = 0; i < 4; i++) {
                int r = m_base + gid + (i & 1) * 8;
                int kk = ks * 8 + tig + (i >> 1) * 4;
                float v = As[r][kk];
                uint32_t hb = f32_to_tf32(v);
                ah[i] = hb;
                al[i] = f32_to_tf32(v - __uint_as_float(hb));
            }
#pragma unroll
            for (int nt = 0; nt < 8; nt++) {
                int c = n_base + nt * 8 + gid;
                uint32_t bh0 = __float_as_uint(Wh[ks * 8 + tig][c]);
                uint32_t bh1 = __float_as_uint(Wh[ks * 8 + tig + 4][c]);
                uint32_t bl0 = __float_as_uint(Wl[ks * 8 + tig][c]);
                uint32_t bl1 = __float_as_uint(Wl[ks * 8 + tig + 4][c]);
                mma_tf32(d[nt], ah, bh0, bh1);
                mma_tf32(d[nt], al, bh0, bh1);
                mma_tf32(d[nt], ah, bl0, bl1);
            }
        }
        __syncthreads();
    }

#pragma unroll
    for (int nt = 0; nt < 8; nt++) {
        int c0 = n_base + nt * 8 + 2 * tig;
#pragma unroll
        for (int i = 0; i < 4; i++) {
            int row = row0 + m_base + gid + (i >> 1) * 8;
            int col = c0 + (i & 1);
            if (row < NNODES) {
                float sc = (PHASE == 0) ? g_norm_src[row] : 1.0f;
                O[(size_t)row * HID + col] =
                    fmaxf(d[nt][i] + __ldg(&bias[col]), 0.0f) * sc;
            }
        }
    }
}

// ---------------- pooling: segmented sum, graph_ids sorted, float4 lanes ------
__global__ __launch_bounds__(128) void pool_kernel(const int* __restrict__ gid) {
    const float4* __restrict__ h4 = (const float4*)g_ha;
    int q = threadIdx.x & 31;
    int sub = threadIdx.x >> 5;
    int n0 = blockIdx.x * 64 + sub * 16;
    int nend = n0 + 16;
    if (nend > NNODES) nend = NNODES;
    if (n0 >= NNODES) return;
    float4 acc = make_float4(0.f, 0.f, 0.f, 0.f);
    int cacc = 0;
    int cur = __ldg(&gid[n0]);
    for (int n = n0; n < nend; n++) {
        int g = __ldg(&gid[n]);
        if (g != cur) {
            red_add_v4(&g_hg[cur * HID + q * 4], acc);
            if (q == 0) atomicAdd(&g_cnt[cur], (float)cacc);
            acc = make_float4(0.f, 0.f, 0.f, 0.f); cacc = 0; cur = g;
        }
        float4 v = h4[(size_t)n * 32 + q];
        acc.x += v.x; acc.y += v.y; acc.z += v.z; acc.w += v.w;
        cacc++;
    }
    red_add_v4(&g_hg[cur * HID + q * 4], acc);
    if (q == 0) atomicAdd(&g_cnt[cur], (float)cacc);
}

// ---------------- classifier: out = (hg/cnt) @ Wc + bc ----------------
__global__ __launch_bounds__(256) void cls_kernel(const float* __restrict__ Wc,
                                                  const float* __restrict__ bc,
                                                  float* __restrict__ out) {
    int g = blockIdx.x * (blockDim.x >> 5) + (threadIdx.x >> 5);
    int lane = threadIdx.x & 31;
    if (g >= NGRAPHS) return;
    float inv = 1.0f / fmaxf(g_cnt[g], 1.0f);
    float x[4];
#pragma unroll
    for (int j = 0; j < 4; j++) x[j] = g_hg[g * HID + lane + j * 32] * inv;
#pragma unroll
    for (int cls = 0; cls < NCLS; cls++) {
        float p = 0.f;
#pragma unroll
        for (int j = 0; j < 4; j++) p += x[j] * __ldg(&Wc[(lane + j * 32) * NCLS + cls]);
#pragma unroll
        for (int o = 16; o; o >>= 1) p += __shfl_xor_sync(0xffffffffu, p, o);
        if (lane == 0) out[g * NCLS + cls] = p + __ldg(&bc[cls]);
    }
}

// ---------------- launch ----------------
extern "C" void kernel_launch(void* const* d_in, const int* in_sizes, int n_in,
                              void* d_out, int out_size) {
    const float* W0 = (const float*)d_in[0];
    const float* b0 = (const float*)d_in[1];
    const float* W1 = (const float*)d_in[2];
    const float* b1 = (const float*)d_in[3];
    const float* W2 = (const float*)d_in[4];
    const float* b2 = (const float*)d_in[5];
    const float* Wc = (const float*)d_in[6];
    const float* bc = (const float*)d_in[7];
    const int* src = (const int*)d_in[8];
    const int* dst = (const int*)d_in[9];
    const int* gid = (const int*)d_in[10];
    float* out = (float*)d_out;

    const int EB = (NEDGES + 255) / 256;
    const int NB = (NNODES + 255) / 256;       // == SCAN_B
    const int ZB = (NGRAPHS * HID + 255) / 256;
    const int WB = (NNODES * 32 + 255) / 256;
    const int GB = (NNODES + 63) / 64;

    zero_kernel<<<ZB, 256>>>();
    degree_kernel<<<EB, 256>>>(src, dst);
    norm_kernel<<<NB, 256>>>();
    scan_a_kernel<<<SCAN_B, 256>>>();
    scan_b_kernel<<<1, 256>>>();
    scan_c_kernel<<<SCAN_B, 256>>>();
    fill_kernel<<<EB, 256>>>(src, dst);

    gather0_dense_kernel<<<WB, 256>>>(W0, b0);

    gather_kernel<0><<<WB, 256>>>();
    gemm_tf32_kernel<0><<<GB, 256>>>(W1, b1);

    gather_kernel<1><<<WB, 256>>>();
    gemm_tf32_kernel<1><<<GB, 256>>>(W2, b2);

    pool_kernel<<<GB, 128>>>(gid);
    cls_kernel<<<(NGRAPHS + 7) / 8, 256>>>(Wc, bc, out);
}

// round 11
// speedup vs baseline: 1.0804x; 1.0804x over previous
#include <cuda_runtime.h>
#include <cuda_fp16.h>
#include <cstdint>

#define NNODES 50000
#define NEDGES 800000
#define NGRAPHS 512
#define HID 128
#define NCLS 10
#define SCAN_B ((NNODES + 255) / 256)   // 196 scan blocks

// ---------------- scratch (device globals; no allocs allowed) ----------------
__device__ float g_deg_in[NNODES];
__device__ float g_deg_out[NNODES];
__device__ float g_norm_src[NNODES];
__device__ float g_norm_dst[NNODES];
__device__ __half g_ha16[(size_t)NNODES * HID];   // fp16 gather input, layer 1
__device__ __half g_hb16[(size_t)NNODES * HID];   // fp16 gather input, layer 2
__device__ float g_ha[(size_t)NNODES * HID];      // fp32 final h (pool input)
__device__ float g_aggA[(size_t)NNODES * HID];
__device__ float g_aggB[(size_t)NNODES * HID];
__device__ float g_hg[NGRAPHS * HID];
__device__ float g_cnt[NGRAPHS];
// CSR by destination
__device__ int g_off[NNODES + 1];
__device__ int g_cursor[NNODES];
__device__ int g_eidx[NEDGES];
__device__ int g_bsum[SCAN_B];
__device__ int g_boff[SCAN_B];

__device__ __forceinline__ void red_add_v4(float* addr, float4 v) {
    asm volatile("red.global.add.v4.f32 [%0], {%1,%2,%3,%4};"
                 :: "l"(addr), "f"(v.x), "f"(v.y), "f"(v.z), "f"(v.w) : "memory");
}

__device__ __forceinline__ uint32_t f32_to_tf32(float v) {
    uint32_t r;
    asm("cvt.rna.tf32.f32 %0, %1;" : "=r"(r) : "f"(v));
    return r;
}

__device__ __forceinline__ void mma_tf32(float d[4], const uint32_t a[4],
                                         uint32_t b0, uint32_t b1) {
    asm volatile("mma.sync.aligned.m16n8k8.row.col.f32.tf32.tf32.f32 "
                 "{%0,%1,%2,%3}, {%4,%5,%6,%7}, {%8,%9}, {%0,%1,%2,%3};"
                 : "+f"(d[0]), "+f"(d[1]), "+f"(d[2]), "+f"(d[3])
                 : "r"(a[0]), "r"(a[1]), "r"(a[2]), "r"(a[3]), "r"(b0), "r"(b1));
}

// pack 4 floats -> uint2 of half2
__device__ __forceinline__ uint2 pack_h4(float x, float y, float z, float w) {
    __half2 p0 = __floats2half2_rn(x, y);
    __half2 p1 = __floats2half2_rn(z, w);
    uint2 u;
    u.x = *(uint32_t*)&p0;
    u.y = *(uint32_t*)&p1;
    return u;
}

// ---------------- zero all accumulated state ----------------
__global__ __launch_bounds__(256) void zero_kernel() {
    int i = blockIdx.x * blockDim.x + threadIdx.x;     // 0..65535
    if (i < NNODES) { g_deg_in[i] = 0.f; g_deg_out[i] = 0.f; g_cursor[i] = 0; }
    if (i < NGRAPHS * HID) g_hg[i] = 0.f;
    if (i < NGRAPHS) g_cnt[i] = 0.f;
}

// ---------------- degree histograms ----------------
__global__ __launch_bounds__(256) void degree_kernel(const int* __restrict__ src,
                                                     const int* __restrict__ dst) {
    int e = blockIdx.x * blockDim.x + threadIdx.x;
    if (e < NEDGES) {
        atomicAdd(&g_deg_out[src[e]], 1.0f);
        atomicAdd(&g_deg_in[dst[e]], 1.0f);
    }
}

// ---------------- norms ----------------
__global__ __launch_bounds__(256) void norm_kernel() {
    int i = blockIdx.x * blockDim.x + threadIdx.x;
    if (i < NNODES) {
        g_norm_src[i] = rsqrtf(fmaxf(g_deg_out[i], 1.0f));
        g_norm_dst[i] = rsqrtf(fmaxf(g_deg_in[i], 1.0f));
    }
}

// ---------------- scan stage A ----------------
__global__ __launch_bounds__(256) void scan_a_kernel() {
    __shared__ int wsum[8];
    int t = threadIdx.x, lane = t & 31, wid = t >> 5;
    int i = blockIdx.x * 256 + t;
    int v = (i < NNODES) ? (int)g_deg_in[i] : 0;
    int x = v;
#pragma unroll
    for (int o = 1; o < 32; o <<= 1) { int y = __shfl_up_sync(~0u, x, o); if (lane >= o) x += y; }
    if (lane == 31) wsum[wid] = x;
    __syncthreads();
    if (wid == 0 && lane < 8) {
        int w = wsum[lane];
#pragma unroll
        for (int o = 1; o < 8; o <<= 1) { int y = __shfl_up_sync(0xffu, w, o); if (lane >= o) w += y; }
        wsum[lane] = w;
    }
    __syncthreads();
    int incl = x + (wid ? wsum[wid - 1] : 0);
    if (i < NNODES) g_off[i] = incl - v;
    if (t == 255) g_bsum[blockIdx.x] = incl;
}

// ---------------- scan stage B ----------------
__global__ __launch_bounds__(256) void scan_b_kernel() {
    __shared__ int wsum[8];
    int t = threadIdx.x, lane = t & 31, wid = t >> 5;
    int v = (t < SCAN_B) ? g_bsum[t] : 0;
    int x = v;
#pragma unroll
    for (int o = 1; o < 32; o <<= 1) { int y = __shfl_up_sync(~0u, x, o); if (lane >= o) x += y; }
    if (lane == 31) wsum[wid] = x;
    __syncthreads();
    if (wid == 0 && lane < 8) {
        int w = wsum[lane];
#pragma unroll
        for (int o = 1; o < 8; o <<= 1) { int y = __shfl_up_sync(0xffu, w, o); if (lane >= o) w += y; }
        wsum[lane] = w;
    }
    __syncthreads();
    int incl = x + (wid ? wsum[wid - 1] : 0);
    if (t < SCAN_B) g_boff[t] = incl - v;
    if (t == SCAN_B - 1) g_off[NNODES] = incl;
}

// ---------------- scan stage C ----------------
__global__ __launch_bounds__(256) void scan_c_kernel() {
    int i = blockIdx.x * 256 + threadIdx.x;
    if (i < NNODES && blockIdx.x > 0) g_off[i] += g_boff[blockIdx.x];
}

// ---------------- CSR fill ----------------
__global__ __launch_bounds__(256) void fill_kernel(const int* __restrict__ src,
                                                   const int* __restrict__ dst) {
    int e = blockIdx.x * blockDim.x + threadIdx.x;
    if (e < NEDGES) {
        int d = dst[e];
        int p = atomicAdd(&g_cursor[d], 1);
        g_eidx[g_off[d] + p] = src[e];
    }
}

// ---------------- layer 0: gather scalar + dense, fused; writes fp16 ha -------
__global__ __launch_bounds__(256) void gather0_dense_kernel(const float* __restrict__ W0,
                                                            const float* __restrict__ b0) {
    int node = (blockIdx.x * blockDim.x + threadIdx.x) >> 5;
    int lane = threadIdx.x & 31;
    if (node >= NNODES) return;
    int beg = g_off[node], end = g_off[node + 1];
    float a = 0.f;
    for (int j = beg + lane; j < end; j += 32) {
        int s = g_eidx[j];
        a += g_deg_in[s] * g_norm_src[s];
    }
#pragma unroll
    for (int o = 16; o; o >>= 1) a += __shfl_xor_sync(~0u, a, o);
    a *= g_norm_dst[node];
    float ns = g_norm_src[node];
    float4 w = __ldg(&((const float4*)W0)[lane]);
    float4 b = __ldg(&((const float4*)b0)[lane]);
    uint2 u = pack_h4(fmaxf(a * w.x + b.x, 0.f) * ns,
                      fmaxf(a * w.y + b.y, 0.f) * ns,
                      fmaxf(a * w.z + b.z, 0.f) * ns,
                      fmaxf(a * w.w + b.w, 0.f) * ns);
    ((uint2*)(g_ha16))[(size_t)node * 32 + lane] = u;
}

// ---------------- CSR gather (fp16 in, fp32 agg out), 2-deep ------------------
template <int PHASE>
__global__ __launch_bounds__(256) void gather_kernel() {
    const uint2* __restrict__ h = (const uint2*)(PHASE == 0 ? g_ha16 : g_hb16);
    float4* __restrict__ agg = (float4*)(PHASE == 0 ? g_aggA : g_aggB);
    int node = (blockIdx.x * blockDim.x + threadIdx.x) >> 5;
    int lane = threadIdx.x & 31;
    if (node >= NNODES) return;
    int beg = g_off[node], end = g_off[node + 1];
    float4 a0 = make_float4(0.f, 0.f, 0.f, 0.f);
    float4 a1 = make_float4(0.f, 0.f, 0.f, 0.f);
    for (int j = beg; j < end; j += 32) {
        int n = end - j;
        int myidx = (lane < n) ? __ldg(&g_eidx[j + lane]) : 0;
        int cnt = n < 32 ? n : 32;
        int k = 0;
        for (; k + 1 < cnt; k += 2) {
            int s0 = __shfl_sync(~0u, myidx, k);
            int s1 = __shfl_sync(~0u, myidx, k + 1);
            uint2 u0 = __ldg(&h[(size_t)s0 * 32 + lane]);
            uint2 u1 = __ldg(&h[(size_t)s1 * 32 + lane]);
            float2 f00 = __half22float2(*(__half2*)&u0.x);
            float2 f01 = __half22float2(*(__half2*)&u0.y);
            float2 f10 = __half22float2(*(__half2*)&u1.x);
            float2 f11 = __half22float2(*(__half2*)&u1.y);
            a0.x += f00.x; a0.y += f00.y; a0.z += f01.x; a0.w += f01.y;
            a1.x += f10.x; a1.y += f10.y; a1.z += f11.x; a1.w += f11.y;
        }
        if (k < cnt) {
            int s0 = __shfl_sync(~0u, myidx, k);
            uint2 u0 = __ldg(&h[(size_t)s0 * 32 + lane]);
            float2 f00 = __half22float2(*(__half2*)&u0.x);
            float2 f01 = __half22float2(*(__half2*)&u0.y);
            a0.x += f00.x; a0.y += f00.y; a0.z += f01.x; a0.w += f01.y;
        }
    }
    a0.x += a1.x; a0.y += a1.y; a0.z += a1.z; a0.w += a1.w;
    agg[(size_t)node * 32 + lane] = a0;
}

// ---------------- GEMM via 3xTF32 mma.sync -------------------------------------
// PHASE 0: agg=g_aggA -> out g_hb16 (fp16, scaled by norm_src)
// PHASE 1: agg=g_aggB -> out g_ha (fp32, unscaled; pool input)
template <int PHASE>
__global__ __launch_bounds__(256) void gemm_tf32_kernel(const float* __restrict__ W,
                                                        const float* __restrict__ bias) {
    const float* __restrict__ A = (PHASE == 0) ? g_aggA : g_aggB;

    __shared__ float As[64][36];
    __shared__ float Wh[32][136];
    __shared__ float Wl[32][136];

    int t = threadIdx.x;
    int w = t >> 5, lane = t & 31;
    int gid = lane >> 2, tig = lane & 3;
    int m_base = (w >> 1) * 16;
    int n_base = (w & 1) * 64;
    int row0 = blockIdx.x * 64;

    float d[8][4];
#pragma unroll
    for (int nt = 0; nt < 8; nt++)
#pragma unroll
        for (int i = 0; i < 4; i++) d[nt][i] = 0.f;

    for (int k0 = 0; k0 < HID; k0 += 32) {
#pragma unroll
        for (int i = 0; i < 16; i++) {
            int idx = t + i * 256;
            int r = idx >> 7, c = idx & 127;
            float v = W[(size_t)(k0 + r) * HID + c];
            uint32_t hb = f32_to_tf32(v);
            float hf = __uint_as_float(hb);
            uint32_t lb = f32_to_tf32(v - hf);
            Wh[r][c] = hf;
            Wl[r][c] = __uint_as_float(lb);
        }
#pragma unroll
        for (int i = 0; i < 8; i++) {
            int idx = t + i * 256;
            int r = idx >> 5, kk = idx & 31;
            int row = row0 + r;
            float v = 0.f;
            if (row < NNODES) v = A[(size_t)row * HID + k0 + kk] * g_norm_dst[row];
            As[r][kk] = v;
        }
        __syncthreads();

#pragma unroll
        for (int ks = 0; ks < 4; ks++) {
            uint32_t ah[4], al[4];
#pragma unroll
            for (int i = 0; i < 4; i++) {
                int r = m_base + gid + (i & 1) * 8;
                int kk = ks * 8 + tig + (i >> 1) * 4;
                float v = As[r][kk];
                uint32_t hb = f32_to_tf32(v);
                ah[i] = hb;
                al[i] = f32_to_tf32(v - __uint_as_float(hb));
            }
#pragma unroll
            for (int nt = 0; nt < 8; nt++) {
                int c = n_base + nt * 8 + gid;
                uint32_t bh0 = __float_as_uint(Wh[ks * 8 + tig][c]);
                uint32_t bh1 = __float_as_uint(Wh[ks * 8 + tig + 4][c]);
                uint32_t bl0 = __float_as_uint(Wl[ks * 8 + tig][c]);
                uint32_t bl1 = __float_as_uint(Wl[ks * 8 + tig + 4][c]);
                mma_tf32(d[nt], ah, bh0, bh1);
                mma_tf32(d[nt], al, bh0, bh1);
                mma_tf32(d[nt], ah, bl0, bl1);
            }
        }
        __syncthreads();
    }

#pragma unroll
    for (int nt = 0; nt < 8; nt++) {
        int c0 = n_base + nt * 8 + 2 * tig;
#pragma unroll
        for (int i = 0; i < 4; i++) {
            int row = row0 + m_base + gid + (i >> 1) * 8;
            int col = c0 + (i & 1);
            if (row < NNODES) {
                float val = fmaxf(d[nt][i] + __ldg(&bias[col]), 0.0f);
                if (PHASE == 0) {
                    g_hb16[(size_t)row * HID + col] = __float2half(val * g_norm_src[row]);
                } else {
                    g_ha[(size_t)row * HID + col] = val;
                }
            }
        }
    }
}

// ---------------- pooling: segmented sum, graph_ids sorted, float4 lanes ------
__global__ __launch_bounds__(128) void pool_kernel(const int* __restrict__ gid) {
    const float4* __restrict__ h4 = (const float4*)g_ha;
    int q = threadIdx.x & 31;
    int sub = threadIdx.x >> 5;
    int n0 = blockIdx.x * 64 + sub * 16;
    int nend = n0 + 16;
    if (nend > NNODES) nend = NNODES;
    if (n0 >= NNODES) return;
    float4 acc = make_float4(0.f, 0.f, 0.f, 0.f);
    int cacc = 0;
    int cur = __ldg(&gid[n0]);
    for (int n = n0; n < nend; n++) {
        int g = __ldg(&gid[n]);
        if (g != cur) {
            red_add_v4(&g_hg[cur * HID + q * 4], acc);
            if (q == 0) atomicAdd(&g_cnt[cur], (float)cacc);
            acc = make_float4(0.f, 0.f, 0.f, 0.f); cacc = 0; cur = g;
        }
        float4 v = h4[(size_t)n * 32 + q];
        acc.x += v.x; acc.y += v.y; acc.z += v.z; acc.w += v.w;
        cacc++;
    }
    red_add_v4(&g_hg[cur * HID + q * 4], acc);
    if (q == 0) atomicAdd(&g_cnt[cur], (float)cacc);
}

// ---------------- classifier: out = (hg/cnt) @ Wc + bc ----------------
__global__ __launch_bounds__(256) void cls_kernel(const float* __restrict__ Wc,
                                                  const float* __restrict__ bc,
                                                  float* __restrict__ out) {
    int g = blockIdx.x * (blockDim.x >> 5) + (threadIdx.x >> 5);
    int lane = threadIdx.x & 31;
    if (g >= NGRAPHS) return;
    float inv = 1.0f / fmaxf(g_cnt[g], 1.0f);
    float x[4];
#pragma unroll
    for (int j = 0; j < 4; j++) x[j] = g_hg[g * HID + lane + j * 32] * inv;
#pragma unroll
    for (int cls = 0; cls < NCLS; cls++) {
        float p = 0.f;
#pragma unroll
        for (int j = 0; j < 4; j++) p += x[j] * __ldg(&Wc[(lane + j * 32) * NCLS + cls]);
#pragma unroll
        for (int o = 16; o; o >>= 1) p += __shfl_xor_sync(0xffffffffu, p, o);
        if (lane == 0) out[g * NCLS + cls] = p + __ldg(&bc[cls]);
    }
}

// ---------------- launch ----------------
extern "C" void kernel_launch(void* const* d_in, const int* in_sizes, int n_in,
                              void* d_out, int out_size) {
    const float* W0 = (const float*)d_in[0];
    const float* b0 = (const float*)d_in[1];
    const float* W1 = (const float*)d_in[2];
    const float* b1 = (const float*)d_in[3];
    const float* W2 = (const float*)d_in[4];
    const float* b2 = (const float*)d_in[5];
    const float* Wc = (const float*)d_in[6];
    const float* bc = (const float*)d_in[7];
    const int* src = (const int*)d_in[8];
    const int* dst = (const int*)d_in[9];
    const int* gid = (const int*)d_in[10];
    float* out = (float*)d_out;

    const int EB = (NEDGES + 255) / 256;
    const int NB = (NNODES + 255) / 256;       // == SCAN_B
    const int ZB = (NGRAPHS * HID + 255) / 256;
    const int WB = (NNODES * 32 + 255) / 256;
    const int GB = (NNODES + 63) / 64;

    zero_kernel<<<ZB, 256>>>();
    degree_kernel<<<EB, 256>>>(src, dst);
    norm_kernel<<<NB, 256>>>();
    scan_a_kernel<<<SCAN_B, 256>>>();
    scan_b_kernel<<<1, 256>>>();
    scan_c_kernel<<<SCAN_B, 256>>>();
    fill_kernel<<<EB, 256>>>(src, dst);

    gather0_dense_kernel<<<WB, 256>>>(W0, b0);

    gather_kernel<0><<<WB, 256>>>();
    gemm_tf32_kernel<0><<<GB, 256>>>(W1, b1);

    gather_kernel<1><<<WB, 256>>>();
    gemm_tf32_kernel<1><<<GB, 256>>>(W2, b2);

    pool_kernel<<<GB, 128>>>(gid);
    cls_kernel<<<(NGRAPHS + 7) / 8, 256>>>(Wc, bc, out);
}

// round 12
// speedup vs baseline: 1.1007x; 1.0187x over previous
#include <cuda_runtime.h>
#include <cuda_fp16.h>
#include <cstdint>

#define NNODES 50000
#define NEDGES 800000
#define NGRAPHS 512
#define HID 128
#define NCLS 10
#define SCAN_B ((NNODES + 255) / 256)   // 196 scan blocks

// ---------------- scratch (device globals; no allocs allowed) ----------------
__device__ float g_deg_in[NNODES];
__device__ float g_deg_out[NNODES];
__device__ float g_norm_src[NNODES];
__device__ float g_norm_dst[NNODES];
__device__ __half g_ha16[(size_t)NNODES * HID];   // fp16 gather input, layer 1
__device__ __half g_hb16[(size_t)NNODES * HID];   // fp16 gather input, layer 2
__device__ float g_ha[(size_t)NNODES * HID];      // fp32 final h (pool input)
__device__ float g_hg[NGRAPHS * HID];
__device__ float g_cnt[NGRAPHS];
// CSR by destination
__device__ int g_off[NNODES + 1];
__device__ int g_cursor[NNODES];
__device__ int g_eidx[NEDGES];
__device__ int g_bsum[SCAN_B];
__device__ int g_boff[SCAN_B];

__device__ __forceinline__ void red_add_v4(float* addr, float4 v) {
    asm volatile("red.global.add.v4.f32 [%0], {%1,%2,%3,%4};"
                 :: "l"(addr), "f"(v.x), "f"(v.y), "f"(v.z), "f"(v.w) : "memory");
}

// fp16 MMA m16n8k16, fp32 accum
__device__ __forceinline__ void mma_f16(float d[4], const uint32_t a[4],
                                        uint32_t b0, uint32_t b1) {
    asm volatile("mma.sync.aligned.m16n8k16.row.col.f32.f16.f16.f32 "
                 "{%0,%1,%2,%3}, {%4,%5,%6,%7}, {%8,%9}, {%0,%1,%2,%3};"
                 : "+f"(d[0]), "+f"(d[1]), "+f"(d[2]), "+f"(d[3])
                 : "r"(a[0]), "r"(a[1]), "r"(a[2]), "r"(a[3]), "r"(b0), "r"(b1));
}

// pack 4 floats -> uint2 of half2
__device__ __forceinline__ uint2 pack_h4(float x, float y, float z, float w) {
    __half2 p0 = __floats2half2_rn(x, y);
    __half2 p1 = __floats2half2_rn(z, w);
    uint2 u;
    u.x = *(uint32_t*)&p0;
    u.y = *(uint32_t*)&p1;
    return u;
}

// ---------------- zero all accumulated state ----------------
__global__ __launch_bounds__(256) void zero_kernel() {
    int i = blockIdx.x * blockDim.x + threadIdx.x;     // 0..65535
    if (i < NNODES) { g_deg_in[i] = 0.f; g_deg_out[i] = 0.f; g_cursor[i] = 0; }
    if (i < NGRAPHS * HID) g_hg[i] = 0.f;
    if (i < NGRAPHS) g_cnt[i] = 0.f;
}

// ---------------- degree histograms ----------------
__global__ __launch_bounds__(256) void degree_kernel(const int* __restrict__ src,
                                                     const int* __restrict__ dst) {
    int e = blockIdx.x * blockDim.x + threadIdx.x;
    if (e < NEDGES) {
        atomicAdd(&g_deg_out[src[e]], 1.0f);
        atomicAdd(&g_deg_in[dst[e]], 1.0f);
    }
}

// ---------------- norms ----------------
__global__ __launch_bounds__(256) void norm_kernel() {
    int i = blockIdx.x * blockDim.x + threadIdx.x;
    if (i < NNODES) {
        g_norm_src[i] = rsqrtf(fmaxf(g_deg_out[i], 1.0f));
        g_norm_dst[i] = rsqrtf(fmaxf(g_deg_in[i], 1.0f));
    }
}

// ---------------- scan stage A ----------------
__global__ __launch_bounds__(256) void scan_a_kernel() {
    __shared__ int wsum[8];
    int t = threadIdx.x, lane = t & 31, wid = t >> 5;
    int i = blockIdx.x * 256 + t;
    int v = (i < NNODES) ? (int)g_deg_in[i] : 0;
    int x = v;
#pragma unroll
    for (int o = 1; o < 32; o <<= 1) { int y = __shfl_up_sync(~0u, x, o); if (lane >= o) x += y; }
    if (lane == 31) wsum[wid] = x;
    __syncthreads();
    if (wid == 0 && lane < 8) {
        int w = wsum[lane];
#pragma unroll
        for (int o = 1; o < 8; o <<= 1) { int y = __shfl_up_sync(0xffu, w, o); if (lane >= o) w += y; }
        wsum[lane] = w;
    }
    __syncthreads();
    int incl = x + (wid ? wsum[wid - 1] : 0);
    if (i < NNODES) g_off[i] = incl - v;
    if (t == 255) g_bsum[blockIdx.x] = incl;
}

// ---------------- scan stage B ----------------
__global__ __launch_bounds__(256) void scan_b_kernel() {
    __shared__ int wsum[8];
    int t = threadIdx.x, lane = t & 31, wid = t >> 5;
    int v = (t < SCAN_B) ? g_bsum[t] : 0;
    int x = v;
#pragma unroll
    for (int o = 1; o < 32; o <<= 1) { int y = __shfl_up_sync(~0u, x, o); if (lane >= o) x += y; }
    if (lane == 31) wsum[wid] = x;
    __syncthreads();
    if (wid == 0 && lane < 8) {
        int w = wsum[lane];
#pragma unroll
        for (int o = 1; o < 8; o <<= 1) { int y = __shfl_up_sync(0xffu, w, o); if (lane >= o) w += y; }
        wsum[lane] = w;
    }
    __syncthreads();
    int incl = x + (wid ? wsum[wid - 1] : 0);
    if (t < SCAN_B) g_boff[t] = incl - v;
    if (t == SCAN_B - 1) g_off[NNODES] = incl;
}

// ---------------- scan stage C ----------------
__global__ __launch_bounds__(256) void scan_c_kernel() {
    int i = blockIdx.x * 256 + threadIdx.x;
    if (i < NNODES && blockIdx.x > 0) g_off[i] += g_boff[blockIdx.x];
}

// ---------------- CSR fill ----------------
__global__ __launch_bounds__(256) void fill_kernel(const int* __restrict__ src,
                                                   const int* __restrict__ dst) {
    int e = blockIdx.x * blockDim.x + threadIdx.x;
    if (e < NEDGES) {
        int d = dst[e];
        int p = atomicAdd(&g_cursor[d], 1);
        g_eidx[g_off[d] + p] = src[e];
    }
}

// ---------------- layer 0: gather scalar + dense, fused; writes fp16 ha -------
__global__ __launch_bounds__(256) void gather0_dense_kernel(const float* __restrict__ W0,
                                                            const float* __restrict__ b0) {
    int node = (blockIdx.x * blockDim.x + threadIdx.x) >> 5;
    int lane = threadIdx.x & 31;
    if (node >= NNODES) return;
    int beg = g_off[node], end = g_off[node + 1];
    float a = 0.f;
    for (int j = beg + lane; j < end; j += 32) {
        int s = g_eidx[j];
        a += g_deg_in[s] * g_norm_src[s];
    }
#pragma unroll
    for (int o = 16; o; o >>= 1) a += __shfl_xor_sync(~0u, a, o);
    a *= g_norm_dst[node];
    float ns = g_norm_src[node];
    float4 w = __ldg(&((const float4*)W0)[lane]);
    float4 b = __ldg(&((const float4*)b0)[lane]);
    uint2 u = pack_h4(fmaxf(a * w.x + b.x, 0.f) * ns,
                      fmaxf(a * w.y + b.y, 0.f) * ns,
                      fmaxf(a * w.z + b.z, 0.f) * ns,
                      fmaxf(a * w.w + b.w, 0.f) * ns);
    ((uint2*)(g_ha16))[(size_t)node * 32 + lane] = u;
}

// ---------------- fused gather + GEMM (fp16 MMA, W hi/lo split) ---------------
// PHASE 0: gather g_ha16 -> A; out = relu(A*nd @ W + b)*ns -> g_hb16
// PHASE 1: gather g_hb16 -> A; out = relu(A*nd @ W + b)    -> g_ha (fp32)
template <int PHASE>
__global__ __launch_bounds__(256) void fused_gemm_kernel(const float* __restrict__ W,
                                                         const float* __restrict__ bias) {
    const uint2* __restrict__ hsrc = (const uint2*)(PHASE == 0 ? g_ha16 : g_hb16);

    __shared__ __half As16[64][136];   // A tile (fp16, scaled by norm_dst)
    __shared__ __half Wh16[128][40];   // W hi, transposed [n][k-chunk]
    __shared__ __half Wl16[128][40];   // W lo residual

    int t = threadIdx.x;
    int w = t >> 5, lane = t & 31;
    int gid = lane >> 2, tig = lane & 3;
    int m_base = (w >> 1) * 16;
    int n_base = (w & 1) * 64;
    int row0 = blockIdx.x * 64;

    // ---- gather: warp w fills rows w*8 .. w*8+7 of As16 ----
#pragma unroll 1
    for (int i = 0; i < 8; i++) {
        int r = w * 8 + i;
        int node = row0 + r;
        float4 a0 = make_float4(0.f, 0.f, 0.f, 0.f);
        float4 a1 = make_float4(0.f, 0.f, 0.f, 0.f);
        if (node < NNODES) {
            int beg = g_off[node], end = g_off[node + 1];
            for (int j = beg; j < end; j += 32) {
                int n = end - j;
                int myidx = (lane < n) ? __ldg(&g_eidx[j + lane]) : 0;
                int cnt = n < 32 ? n : 32;
                int k = 0;
                for (; k + 1 < cnt; k += 2) {
                    int s0 = __shfl_sync(~0u, myidx, k);
                    int s1 = __shfl_sync(~0u, myidx, k + 1);
                    uint2 u0 = __ldg(&hsrc[(size_t)s0 * 32 + lane]);
                    uint2 u1 = __ldg(&hsrc[(size_t)s1 * 32 + lane]);
                    float2 f00 = __half22float2(*(__half2*)&u0.x);
                    float2 f01 = __half22float2(*(__half2*)&u0.y);
                    float2 f10 = __half22float2(*(__half2*)&u1.x);
                    float2 f11 = __half22float2(*(__half2*)&u1.y);
                    a0.x += f00.x; a0.y += f00.y; a0.z += f01.x; a0.w += f01.y;
                    a1.x += f10.x; a1.y += f10.y; a1.z += f11.x; a1.w += f11.y;
                }
                if (k < cnt) {
                    int s0 = __shfl_sync(~0u, myidx, k);
                    uint2 u0 = __ldg(&hsrc[(size_t)s0 * 32 + lane]);
                    float2 f00 = __half22float2(*(__half2*)&u0.x);
                    float2 f01 = __half22float2(*(__half2*)&u0.y);
                    a0.x += f00.x; a0.y += f00.y; a0.z += f01.x; a0.w += f01.y;
                }
            }
            float nd = g_norm_dst[node];
            a0.x = (a0.x + a1.x) * nd;
            a0.y = (a0.y + a1.y) * nd;
            a0.z = (a0.z + a1.z) * nd;
            a0.w = (a0.w + a1.w) * nd;
        }
        uint2 u = pack_h4(a0.x, a0.y, a0.z, a0.w);
        *(uint2*)&As16[r][lane * 4] = u;
    }
    __syncthreads();

    float d[8][4];
#pragma unroll
    for (int nt = 0; nt < 8; nt++)
#pragma unroll
        for (int i = 0; i < 4; i++) d[nt][i] = 0.f;

    for (int k0 = 0; k0 < HID; k0 += 32) {
        // stage W chunk hi/lo, transposed: Wh16[n][k] for k = k0..k0+31
#pragma unroll
        for (int i = 0; i < 16; i++) {
            int idx = t + i * 256;                  // 4096 = 32k x 128n
            int k = idx >> 7, n = idx & 127;
            float v = W[(size_t)(k0 + k) * HID + n];
            __half h = __float2half(v);
            __half l = __float2half(v - __half2float(h));
            Wh16[n][k] = h;
            Wl16[n][k] = l;
        }
        __syncthreads();

#pragma unroll
        for (int ks = 0; ks < 2; ks++) {
            int kb = k0 + ks * 16;
            uint32_t a[4];
            a[0] = *(const uint32_t*)&As16[m_base + gid][kb + 2 * tig];
            a[1] = *(const uint32_t*)&As16[m_base + gid + 8][kb + 2 * tig];
            a[2] = *(const uint32_t*)&As16[m_base + gid][kb + 2 * tig + 8];
            a[3] = *(const uint32_t*)&As16[m_base + gid + 8][kb + 2 * tig + 8];
            int kl = ks * 16;
#pragma unroll
            for (int nt = 0; nt < 8; nt++) {
                int n = n_base + nt * 8 + gid;
                uint32_t bh0 = *(const uint32_t*)&Wh16[n][kl + 2 * tig];
                uint32_t bh1 = *(const uint32_t*)&Wh16[n][kl + 2 * tig + 8];
                uint32_t bl0 = *(const uint32_t*)&Wl16[n][kl + 2 * tig];
                uint32_t bl1 = *(const uint32_t*)&Wl16[n][kl + 2 * tig + 8];
                mma_f16(d[nt], a, bh0, bh1);
                mma_f16(d[nt], a, bl0, bl1);
            }
        }
        __syncthreads();
    }

    // epilogue
#pragma unroll
    for (int nt = 0; nt < 8; nt++) {
        int c0 = n_base + nt * 8 + 2 * tig;
#pragma unroll
        for (int half_r = 0; half_r < 2; half_r++) {
            int row = row0 + m_base + gid + half_r * 8;
            if (row < NNODES) {
                float v0 = fmaxf(d[nt][half_r * 2 + 0] + __ldg(&bias[c0]), 0.0f);
                float v1 = fmaxf(d[nt][half_r * 2 + 1] + __ldg(&bias[c0 + 1]), 0.0f);
                if (PHASE == 0) {
                    float ns = g_norm_src[row];
                    __half2 p = __floats2half2_rn(v0 * ns, v1 * ns);
                    *(uint32_t*)&g_hb16[(size_t)row * HID + c0] = *(uint32_t*)&p;
                } else {
                    g_ha[(size_t)row * HID + c0] = v0;
                    g_ha[(size_t)row * HID + c0 + 1] = v1;
                }
            }
        }
    }
}

// ---------------- pooling: segmented sum, graph_ids sorted, float4 lanes ------
__global__ __launch_bounds__(128) void pool_kernel(const int* __restrict__ gid) {
    const float4* __restrict__ h4 = (const float4*)g_ha;
    int q = threadIdx.x & 31;
    int sub = threadIdx.x >> 5;
    int n0 = blockIdx.x * 64 + sub * 16;
    int nend = n0 + 16;
    if (nend > NNODES) nend = NNODES;
    if (n0 >= NNODES) return;
    float4 acc = make_float4(0.f, 0.f, 0.f, 0.f);
    int cacc = 0;
    int cur = __ldg(&gid[n0]);
    for (int n = n0; n < nend; n++) {
        int g = __ldg(&gid[n]);
        if (g != cur) {
            red_add_v4(&g_hg[cur * HID + q * 4], acc);
            if (q == 0) atomicAdd(&g_cnt[cur], (float)cacc);
            acc = make_float4(0.f, 0.f, 0.f, 0.f); cacc = 0; cur = g;
        }
        float4 v = h4[(size_t)n * 32 + q];
        acc.x += v.x; acc.y += v.y; acc.z += v.z; acc.w += v.w;
        cacc++;
    }
    red_add_v4(&g_hg[cur * HID + q * 4], acc);
    if (q == 0) atomicAdd(&g_cnt[cur], (float)cacc);
}

// ---------------- classifier: out = (hg/cnt) @ Wc + bc ----------------
__global__ __launch_bounds__(256) void cls_kernel(const float* __restrict__ Wc,
                                                  const float* __restrict__ bc,
                                                  float* __restrict__ out) {
    int g = blockIdx.x * (blockDim.x >> 5) + (threadIdx.x >> 5);
    int lane = threadIdx.x & 31;
    if (g >= NGRAPHS) return;
    float inv = 1.0f / fmaxf(g_cnt[g], 1.0f);
    float x[4];
#pragma unroll
    for (int j = 0; j < 4; j++) x[j] = g_hg[g * HID + lane + j * 32] * inv;
#pragma unroll
    for (int cls = 0; cls < NCLS; cls++) {
        float p = 0.f;
#pragma unroll
        for (int j = 0; j < 4; j++) p += x[j] * __ldg(&Wc[(lane + j * 32) * NCLS + cls]);
#pragma unroll
        for (int o = 16; o; o >>= 1) p += __shfl_xor_sync(0xffffffffu, p, o);
        if (lane == 0) out[g * NCLS + cls] = p + __ldg(&bc[cls]);
    }
}

// ---------------- launch ----------------
extern "C" void kernel_launch(void* const* d_in, const int* in_sizes, int n_in,
                              void* d_out, int out_size) {
    const float* W0 = (const float*)d_in[0];
    const float* b0 = (const float*)d_in[1];
    const float* W1 = (const float*)d_in[2];
    const float* b1 = (const float*)d_in[3];
    const float* W2 = (const float*)d_in[4];
    const float* b2 = (const float*)d_in[5];
    const float* Wc = (const float*)d_in[6];
    const float* bc = (const float*)d_in[7];
    const int* src = (const int*)d_in[8];
    const int* dst = (const int*)d_in[9];
    const int* gid = (const int*)d_in[10];
    float* out = (float*)d_out;

    const int EB = (NEDGES + 255) / 256;
    const int NB = (NNODES + 255) / 256;       // == SCAN_B
    const int ZB = (NGRAPHS * HID + 255) / 256;
    const int WB = (NNODES * 32 + 255) / 256;
    const int GB = (NNODES + 63) / 64;         // 782 fused-GEMM blocks

    zero_kernel<<<ZB, 256>>>();
    degree_kernel<<<EB, 256>>>(src, dst);
    norm_kernel<<<NB, 256>>>();
    scan_a_kernel<<<SCAN_B, 256>>>();
    scan_b_kernel<<<1, 256>>>();
    scan_c_kernel<<<SCAN_B, 256>>>();
    fill_kernel<<<EB, 256>>>(src, dst);

    gather0_dense_kernel<<<WB, 256>>>(W0, b0);

    fused_gemm_kernel<0><<<GB, 256>>>(W1, b1);
    fused_gemm_kernel<1><<<GB, 256>>>(W2, b2);

    pool_kernel<<<GB, 128>>>(gid);
    cls_kernel<<<(NGRAPHS + 7) / 8, 256>>>(Wc, bc, out);
}

// round 13
// speedup vs baseline: 1.2570x; 1.1420x over previous
#include <cuda_runtime.h>
#include <cuda_fp16.h>
#include <cstdint>

#define NNODES 50000
#define NEDGES 800000
#define NGRAPHS 512
#define HID 128
#define NCLS 10
#define SCAN_B ((NNODES + 255) / 256)   // 196 scan blocks
#define FUSED_SMEM 87040                // (64*68 + 2*128*68) words * 4B

// ---------------- scratch (device globals; no allocs allowed) ----------------
__device__ float g_deg_in[NNODES];
__device__ float g_deg_out[NNODES];
__device__ float g_norm_src[NNODES];
__device__ float g_norm_dst[NNODES];
__device__ __half g_ha16[(size_t)NNODES * HID];   // fp16 gather input, layer 1
__device__ __half g_hb16[(size_t)NNODES * HID];   // fp16 gather input, layer 2
__device__ float g_ha[(size_t)NNODES * HID];      // fp32 final h (pool input)
__device__ float g_hg[NGRAPHS * HID];
__device__ float g_cnt[NGRAPHS];
__device__ __half g_Wh[2 * HID * HID];            // pre-split W hi, transposed [n][k]
__device__ __half g_Wl[2 * HID * HID];            // pre-split W lo residual
// CSR by destination
__device__ int g_off[NNODES + 1];
__device__ int g_cursor[NNODES];
__device__ int g_eidx[NEDGES];
__device__ int g_bsum[SCAN_B];
__device__ int g_boff[SCAN_B];

__device__ __forceinline__ void red_add_v4(float* addr, float4 v) {
    asm volatile("red.global.add.v4.f32 [%0], {%1,%2,%3,%4};"
                 :: "l"(addr), "f"(v.x), "f"(v.y), "f"(v.z), "f"(v.w) : "memory");
}

// fp16 MMA m16n8k16, fp32 accum
__device__ __forceinline__ void mma_f16(float d[4], const uint32_t a[4],
                                        uint32_t b0, uint32_t b1) {
    asm volatile("mma.sync.aligned.m16n8k16.row.col.f32.f16.f16.f32 "
                 "{%0,%1,%2,%3}, {%4,%5,%6,%7}, {%8,%9}, {%0,%1,%2,%3};"
                 : "+f"(d[0]), "+f"(d[1]), "+f"(d[2]), "+f"(d[3])
                 : "r"(a[0]), "r"(a[1]), "r"(a[2]), "r"(a[3]), "r"(b0), "r"(b1));
}

__device__ __forceinline__ uint2 pack_h4(float x, float y, float z, float w) {
    __half2 p0 = __floats2half2_rn(x, y);
    __half2 p1 = __floats2half2_rn(z, w);
    uint2 u;
    u.x = *(uint32_t*)&p0;
    u.y = *(uint32_t*)&p1;
    return u;
}

// ---------------- zero all accumulated state ----------------
__global__ __launch_bounds__(256) void zero_kernel() {
    int i = blockIdx.x * blockDim.x + threadIdx.x;     // 0..65535
    if (i < NNODES) { g_deg_in[i] = 0.f; g_deg_out[i] = 0.f; g_cursor[i] = 0; }
    if (i < NGRAPHS * HID) g_hg[i] = 0.f;
    if (i < NGRAPHS) g_cnt[i] = 0.f;
}

// ---------------- W pre-split: hi/lo fp16, transposed [n][k] ------------------
__global__ __launch_bounds__(256) void wsplit_kernel(const float* __restrict__ W1,
                                                     const float* __restrict__ W2) {
    int i = blockIdx.x * blockDim.x + threadIdx.x;   // 0..32767
    int w = i >> 14, idx = i & 16383;
    int k = idx >> 7, n = idx & 127;
    const float* W = w ? W2 : W1;
    float v = W[k * HID + n];
    __half h = __float2half(v);
    g_Wh[w * HID * HID + n * HID + k] = h;
    g_Wl[w * HID * HID + n * HID + k] = __float2half(v - __half2float(h));
}

// ---------------- degree histograms ----------------
__global__ __launch_bounds__(256) void degree_kernel(const int* __restrict__ src,
                                                     const int* __restrict__ dst) {
    int e = blockIdx.x * blockDim.x + threadIdx.x;
    if (e < NEDGES) {
        atomicAdd(&g_deg_out[src[e]], 1.0f);
        atomicAdd(&g_deg_in[dst[e]], 1.0f);
    }
}

// ---------------- norms ----------------
__global__ __launch_bounds__(256) void norm_kernel() {
    int i = blockIdx.x * blockDim.x + threadIdx.x;
    if (i < NNODES) {
        g_norm_src[i] = rsqrtf(fmaxf(g_deg_out[i], 1.0f));
        g_norm_dst[i] = rsqrtf(fmaxf(g_deg_in[i], 1.0f));
    }
}

// ---------------- scan stage A ----------------
__global__ __launch_bounds__(256) void scan_a_kernel() {
    __shared__ int wsum[8];
    int t = threadIdx.x, lane = t & 31, wid = t >> 5;
    int i = blockIdx.x * 256 + t;
    int v = (i < NNODES) ? (int)g_deg_in[i] : 0;
    int x = v;
#pragma unroll
    for (int o = 1; o < 32; o <<= 1) { int y = __shfl_up_sync(~0u, x, o); if (lane >= o) x += y; }
    if (lane == 31) wsum[wid] = x;
    __syncthreads();
    if (wid == 0 && lane < 8) {
        int w = wsum[lane];
#pragma unroll
        for (int o = 1; o < 8; o <<= 1) { int y = __shfl_up_sync(0xffu, w, o); if (lane >= o) w += y; }
        wsum[lane] = w;
    }
    __syncthreads();
    int incl = x + (wid ? wsum[wid - 1] : 0);
    if (i < NNODES) g_off[i] = incl - v;
    if (t == 255) g_bsum[blockIdx.x] = incl;
}

// ---------------- scan stage B ----------------
__global__ __launch_bounds__(256) void scan_b_kernel() {
    __shared__ int wsum[8];
    int t = threadIdx.x, lane = t & 31, wid = t >> 5;
    int v = (t < SCAN_B) ? g_bsum[t] : 0;
    int x = v;
#pragma unroll
    for (int o = 1; o < 32; o <<= 1) { int y = __shfl_up_sync(~0u, x, o); if (lane >= o) x += y; }
    if (lane == 31) wsum[wid] = x;
    __syncthreads();
    if (wid == 0 && lane < 8) {
        int w = wsum[lane];
#pragma unroll
        for (int o = 1; o < 8; o <<= 1) { int y = __shfl_up_sync(0xffu, w, o); if (lane >= o) w += y; }
        wsum[lane] = w;
    }
    __syncthreads();
    int incl = x + (wid ? wsum[wid - 1] : 0);
    if (t < SCAN_B) g_boff[t] = incl - v;
    if (t == SCAN_B - 1) g_off[NNODES] = incl;
}

// ---------------- scan stage C ----------------
__global__ __launch_bounds__(256) void scan_c_kernel() {
    int i = blockIdx.x * 256 + threadIdx.x;
    if (i < NNODES && blockIdx.x > 0) g_off[i] += g_boff[blockIdx.x];
}

// ---------------- CSR fill ----------------
__global__ __launch_bounds__(256) void fill_kernel(const int* __restrict__ src,
                                                   const int* __restrict__ dst) {
    int e = blockIdx.x * blockDim.x + threadIdx.x;
    if (e < NEDGES) {
        int d = dst[e];
        int p = atomicAdd(&g_cursor[d], 1);
        g_eidx[g_off[d] + p] = src[e];
    }
}

// ---------------- layer 0: gather scalar + dense, fused; writes fp16 ha -------
__global__ __launch_bounds__(256) void gather0_dense_kernel(const float* __restrict__ W0,
                                                            const float* __restrict__ b0) {
    int node = (blockIdx.x * blockDim.x + threadIdx.x) >> 5;
    int lane = threadIdx.x & 31;
    if (node >= NNODES) return;
    int beg = g_off[node], end = g_off[node + 1];
    float a = 0.f;
    for (int j = beg + lane; j < end; j += 32) {
        int s = g_eidx[j];
        a += g_deg_in[s] * g_norm_src[s];
    }
#pragma unroll
    for (int o = 16; o; o >>= 1) a += __shfl_xor_sync(~0u, a, o);
    a *= g_norm_dst[node];
    float ns = g_norm_src[node];
    float4 w = __ldg(&((const float4*)W0)[lane]);
    float4 b = __ldg(&((const float4*)b0)[lane]);
    uint2 u = pack_h4(fmaxf(a * w.x + b.x, 0.f) * ns,
                      fmaxf(a * w.y + b.y, 0.f) * ns,
                      fmaxf(a * w.z + b.z, 0.f) * ns,
                      fmaxf(a * w.w + b.w, 0.f) * ns);
    ((uint2*)(g_ha16))[(size_t)node * 32 + lane] = u;
}

// ---------------- fused gather + GEMM (fp16 MMA, pre-split W, 1 barrier) ------
// PHASE 0: gather g_ha16 -> A; out = relu(A*nd @ W1 + b)*ns -> g_hb16
// PHASE 1: gather g_hb16 -> A; out = relu(A*nd @ W2 + b)    -> g_ha (fp32)
// dyn smem (words): As 64*68 | Wh 128*68 | Wl 128*68
template <int PHASE>
__global__ __launch_bounds__(256, 2) void fused_gemm_kernel(const float* __restrict__ bias) {
    const uint2* __restrict__ hsrc = (const uint2*)(PHASE == 0 ? g_ha16 : g_hb16);
    extern __shared__ uint32_t smw[];
    uint32_t* asw = smw;                 // 64*68 = 4352 words
    uint32_t* whw = smw + 4352;          // 128*68 = 8704 words
    uint32_t* wlw = smw + 13056;

    int t = threadIdx.x;
    int w = t >> 5, lane = t & 31;
    int gid = lane >> 2, tig = lane & 3;
    int m_base = (w >> 1) * 16;
    int n_base = (w & 1) * 64;
    int row0 = blockIdx.x * 64;

    // ---- stage pre-split W (coalesced LDG.32, conflict-free STS.32) ----
    const uint32_t* whg = (const uint32_t*)(g_Wh + (size_t)PHASE * HID * HID);
    const uint32_t* wlg = (const uint32_t*)(g_Wl + (size_t)PHASE * HID * HID);
#pragma unroll
    for (int i = 0; i < 32; i++) {
        int idx = t + i * 256;           // 0..8191: n = idx>>6, kw = idx&63
        int n = idx >> 6, kw = idx & 63;
        whw[n * 68 + kw] = __ldg(&whg[idx]);
        wlw[n * 68 + kw] = __ldg(&wlg[idx]);
    }

    // ---- gather: warp w fills rows w*8 .. w*8+7 of As; prefetched offsets ----
    int offv = 0;
    {
        int nidx = row0 + w * 8 + lane;
        if (lane < 9) offv = g_off[nidx <= NNODES ? nidx : NNODES];
    }
    int pb[8], pe[8], pidx[8];
#pragma unroll
    for (int i = 0; i < 8; i++) {
        pb[i] = __shfl_sync(~0u, offv, i);
        pe[i] = __shfl_sync(~0u, offv, i + 1);
        pidx[i] = (pb[i] + lane < pe[i]) ? __ldg(&g_eidx[pb[i] + lane]) : 0;
    }
#pragma unroll
    for (int i = 0; i < 8; i++) {
        int r = w * 8 + i;
        int node = row0 + r;
        float4 a0 = make_float4(0.f, 0.f, 0.f, 0.f);
        float4 a1 = make_float4(0.f, 0.f, 0.f, 0.f);
        if (node < NNODES) {
            int beg = pb[i], end = pe[i];
            int myidx = pidx[i];
            for (int j = beg; j < end; j += 32) {
                if (j != beg) {
                    int n = end - j;
                    myidx = (lane < n) ? __ldg(&g_eidx[j + lane]) : 0;
                }
                int rem = end - j;
                int cnt = rem < 32 ? rem : 32;
                int k = 0;
                for (; k + 1 < cnt; k += 2) {
                    int s0 = __shfl_sync(~0u, myidx, k);
                    int s1 = __shfl_sync(~0u, myidx, k + 1);
                    uint2 u0 = __ldg(&hsrc[(size_t)s0 * 32 + lane]);
                    uint2 u1 = __ldg(&hsrc[(size_t)s1 * 32 + lane]);
                    float2 f00 = __half22float2(*(__half2*)&u0.x);
                    float2 f01 = __half22float2(*(__half2*)&u0.y);
                    float2 f10 = __half22float2(*(__half2*)&u1.x);
                    float2 f11 = __half22float2(*(__half2*)&u1.y);
                    a0.x += f00.x; a0.y += f00.y; a0.z += f01.x; a0.w += f01.y;
                    a1.x += f10.x; a1.y += f10.y; a1.z += f11.x; a1.w += f11.y;
                }
                if (k < cnt) {
                    int s0 = __shfl_sync(~0u, myidx, k);
                    uint2 u0 = __ldg(&hsrc[(size_t)s0 * 32 + lane]);
                    float2 f00 = __half22float2(*(__half2*)&u0.x);
                    float2 f01 = __half22float2(*(__half2*)&u0.y);
                    a0.x += f00.x; a0.y += f00.y; a0.z += f01.x; a0.w += f01.y;
                }
            }
            float nd = g_norm_dst[node];
            a0.x = (a0.x + a1.x) * nd;
            a0.y = (a0.y + a1.y) * nd;
            a0.z = (a0.z + a1.z) * nd;
            a0.w = (a0.w + a1.w) * nd;
        }
        uint2 u = pack_h4(a0.x, a0.y, a0.z, a0.w);
        *(uint2*)&asw[r * 68 + lane * 2] = u;
    }
    __syncthreads();

    // ---- MMA mainloop: no barriers ----
    float d[8][4];
#pragma unroll
    for (int nt = 0; nt < 8; nt++)
#pragma unroll
        for (int i = 0; i < 4; i++) d[nt][i] = 0.f;

#pragma unroll
    for (int kb = 0; kb < 8; kb++) {       // k16 steps
        uint32_t a[4];
        int aw0 = (m_base + gid) * 68 + kb * 8 + tig;
        int aw1 = (m_base + gid + 8) * 68 + kb * 8 + tig;
        a[0] = asw[aw0];
        a[1] = asw[aw1];
        a[2] = asw[aw0 + 4];
        a[3] = asw[aw1 + 4];
#pragma unroll
        for (int nt = 0; nt < 8; nt++) {
            int n = n_base + nt * 8 + gid;
            int bw = n * 68 + kb * 8 + tig;
            uint32_t bh0 = whw[bw];
            uint32_t bh1 = whw[bw + 4];
            uint32_t bl0 = wlw[bw];
            uint32_t bl1 = wlw[bw + 4];
            mma_f16(d[nt], a, bh0, bh1);
            mma_f16(d[nt], a, bl0, bl1);
        }
    }

    // ---- epilogue ----
#pragma unroll
    for (int nt = 0; nt < 8; nt++) {
        int c0 = n_base + nt * 8 + 2 * tig;
#pragma unroll
        for (int half_r = 0; half_r < 2; half_r++) {
            int row = row0 + m_base + gid + half_r * 8;
            if (row < NNODES) {
                float v0 = fmaxf(d[nt][half_r * 2 + 0] + __ldg(&bias[c0]), 0.0f);
                float v1 = fmaxf(d[nt][half_r * 2 + 1] + __ldg(&bias[c0 + 1]), 0.0f);
                if (PHASE == 0) {
                    float ns = g_norm_src[row];
                    __half2 p = __floats2half2_rn(v0 * ns, v1 * ns);
                    *(uint32_t*)&g_hb16[(size_t)row * HID + c0] = *(uint32_t*)&p;
                } else {
                    g_ha[(size_t)row * HID + c0] = v0;
                    g_ha[(size_t)row * HID + c0 + 1] = v1;
                }
            }
        }
    }
}

// ---------------- pooling: segmented sum, graph_ids sorted, float4 lanes ------
__global__ __launch_bounds__(128) void pool_kernel(const int* __restrict__ gid) {
    const float4* __restrict__ h4 = (const float4*)g_ha;
    int q = threadIdx.x & 31;
    int sub = threadIdx.x >> 5;
    int n0 = blockIdx.x * 64 + sub * 16;
    int nend = n0 + 16;
    if (nend > NNODES) nend = NNODES;
    if (n0 >= NNODES) return;
    float4 acc = make_float4(0.f, 0.f, 0.f, 0.f);
    int cacc = 0;
    int cur = __ldg(&gid[n0]);
    for (int n = n0; n < nend; n++) {
        int g = __ldg(&gid[n]);
        if (g != cur) {
            red_add_v4(&g_hg[cur * HID + q * 4], acc);
            if (q == 0) atomicAdd(&g_cnt[cur], (float)cacc);
            acc = make_float4(0.f, 0.f, 0.f, 0.f); cacc = 0; cur = g;
        }
        float4 v = h4[(size_t)n * 32 + q];
        acc.x += v.x; acc.y += v.y; acc.z += v.z; acc.w += v.w;
        cacc++;
    }
    red_add_v4(&g_hg[cur * HID + q * 4], acc);
    if (q == 0) atomicAdd(&g_cnt[cur], (float)cacc);
}

// ---------------- classifier: out = (hg/cnt) @ Wc + bc ----------------
__global__ __launch_bounds__(256) void cls_kernel(const float* __restrict__ Wc,
                                                  const float* __restrict__ bc,
                                                  float* __restrict__ out) {
    int g = blockIdx.x * (blockDim.x >> 5) + (threadIdx.x >> 5);
    int lane = threadIdx.x & 31;
    if (g >= NGRAPHS) return;
    float inv = 1.0f / fmaxf(g_cnt[g], 1.0f);
    float x[4];
#pragma unroll
    for (int j = 0; j < 4; j++) x[j] = g_hg[g * HID + lane + j * 32] * inv;
#pragma unroll
    for (int cls = 0; cls < NCLS; cls++) {
        float p = 0.f;
#pragma unroll
        for (int j = 0; j < 4; j++) p += x[j] * __ldg(&Wc[(lane + j * 32) * NCLS + cls]);
#pragma unroll
        for (int o = 16; o; o >>= 1) p += __shfl_xor_sync(0xffffffffu, p, o);
        if (lane == 0) out[g * NCLS + cls] = p + __ldg(&bc[cls]);
    }
}

// ---------------- launch ----------------
extern "C" void kernel_launch(void* const* d_in, const int* in_sizes, int n_in,
                              void* d_out, int out_size) {
    const float* W0 = (const float*)d_in[0];
    const float* b0 = (const float*)d_in[1];
    const float* W1 = (const float*)d_in[2];
    const float* b1 = (const float*)d_in[3];
    const float* W2 = (const float*)d_in[4];
    const float* b2 = (const float*)d_in[5];
    const float* Wc = (const float*)d_in[6];
    const float* bc = (const float*)d_in[7];
    const int* src = (const int*)d_in[8];
    const int* dst = (const int*)d_in[9];
    const int* gid = (const int*)d_in[10];
    float* out = (float*)d_out;

    const int EB = (NEDGES + 255) / 256;
    const int NB = (NNODES + 255) / 256;       // == SCAN_B
    const int ZB = (NGRAPHS * HID + 255) / 256;
    const int WB = (NNODES * 32 + 255) / 256;
    const int GB = (NNODES + 63) / 64;         // 782 fused-GEMM blocks

    cudaFuncSetAttribute(fused_gemm_kernel<0>,
                         cudaFuncAttributeMaxDynamicSharedMemorySize, FUSED_SMEM);
    cudaFuncSetAttribute(fused_gemm_kernel<1>,
                         cudaFuncAttributeMaxDynamicSharedMemorySize, FUSED_SMEM);

    zero_kernel<<<ZB, 256>>>();
    degree_kernel<<<EB, 256>>>(src, dst);
    norm_kernel<<<NB, 256>>>();
    scan_a_kernel<<<SCAN_B, 256>>>();
    scan_b_kernel<<<1, 256>>>();
    scan_c_kernel<<<SCAN_B, 256>>>();
    fill_kernel<<<EB, 256>>>(src, dst);
    wsplit_kernel<<<128, 256>>>(W1, W2);

    gather0_dense_kernel<<<WB, 256>>>(W0, b0);

    fused_gemm_kernel<0><<<GB, 256, FUSED_SMEM>>>(b1);
    fused_gemm_kernel<1><<<GB, 256, FUSED_SMEM>>>(b2);

    pool_kernel<<<GB, 128>>>(gid);
    cls_kernel<<<(NGRAPHS + 7) / 8, 256>>>(Wc, bc, out);
}

// round 14
// speedup vs baseline: 1.2692x; 1.0098x over previous
#include <cuda_runtime.h>
#include <cuda_fp16.h>
#include <cstdint>

#define NNODES 50000
#define NEDGES 800000
#define NGRAPHS 512
#define HID 128
#define NCLS 10
#define SCAN_B ((NNODES + 255) / 256)   // 196 scan blocks
#define FUSED_SMEM 87040                // (64*68 + 2*128*68) words * 4B

// ---------------- scratch (device globals; no allocs allowed) ----------------
__device__ float g_deg_in[NNODES];
__device__ float g_deg_out[NNODES];
__device__ float g_norm_src[NNODES];
__device__ float g_norm_dst[NNODES];
__device__ __half g_ha16[(size_t)NNODES * HID];   // fp16 gather input, layer 1
__device__ __half g_hb16[(size_t)NNODES * HID];   // fp16 gather input, layer 2
__device__ float g_ha[(size_t)NNODES * HID];      // fp32 final h (pool input)
__device__ float g_hg[NGRAPHS * HID];
__device__ float g_cnt[NGRAPHS];
__device__ __half g_Wh[2 * HID * HID];            // pre-split W hi, transposed [n][k]
__device__ __half g_Wl[2 * HID * HID];            // pre-split W lo residual
// CSR by destination
__device__ int g_off[NNODES + 1];
__device__ int g_cursor[NNODES];
__device__ int g_eidx[NEDGES];
__device__ int g_bsum[SCAN_B];
__device__ int g_boff[SCAN_B];

__device__ __forceinline__ void red_add_v4(float* addr, float4 v) {
    asm volatile("red.global.add.v4.f32 [%0], {%1,%2,%3,%4};"
                 :: "l"(addr), "f"(v.x), "f"(v.y), "f"(v.z), "f"(v.w) : "memory");
}

// fp16 MMA m16n8k16, fp32 accum
__device__ __forceinline__ void mma_f16(float d[4], const uint32_t a[4],
                                        uint32_t b0, uint32_t b1) {
    asm volatile("mma.sync.aligned.m16n8k16.row.col.f32.f16.f16.f32 "
                 "{%0,%1,%2,%3}, {%4,%5,%6,%7}, {%8,%9}, {%0,%1,%2,%3};"
                 : "+f"(d[0]), "+f"(d[1]), "+f"(d[2]), "+f"(d[3])
                 : "r"(a[0]), "r"(a[1]), "r"(a[2]), "r"(a[3]), "r"(b0), "r"(b1));
}

__device__ __forceinline__ uint2 pack_h4(float x, float y, float z, float w) {
    __half2 p0 = __floats2half2_rn(x, y);
    __half2 p1 = __floats2half2_rn(z, w);
    uint2 u;
    u.x = *(uint32_t*)&p0;
    u.y = *(uint32_t*)&p1;
    return u;
}

// 16B async copy global -> shared (bypasses registers)
__device__ __forceinline__ void cp_async16(uint32_t smem_addr, const void* gptr) {
    asm volatile("cp.async.cg.shared.global [%0], [%1], 16;"
                 :: "r"(smem_addr), "l"(gptr) : "memory");
}

// ---------------- zero all accumulated state ----------------
__global__ __launch_bounds__(256) void zero_kernel() {
    int i = blockIdx.x * blockDim.x + threadIdx.x;     // 0..65535
    if (i < NNODES) { g_deg_in[i] = 0.f; g_deg_out[i] = 0.f; g_cursor[i] = 0; }
    if (i < NGRAPHS * HID) g_hg[i] = 0.f;
    if (i < NGRAPHS) g_cnt[i] = 0.f;
}

// ---------------- W pre-split: hi/lo fp16, transposed [n][k] ------------------
__global__ __launch_bounds__(256) void wsplit_kernel(const float* __restrict__ W1,
                                                     const float* __restrict__ W2) {
    int i = blockIdx.x * blockDim.x + threadIdx.x;   // 0..32767
    int w = i >> 14, idx = i & 16383;
    int k = idx >> 7, n = idx & 127;
    const float* W = w ? W2 : W1;
    float v = W[k * HID + n];
    __half h = __float2half(v);
    g_Wh[w * HID * HID + n * HID + k] = h;
    g_Wl[w * HID * HID + n * HID + k] = __float2half(v - __half2float(h));
}

// ---------------- degree histograms ----------------
__global__ __launch_bounds__(256) void degree_kernel(const int* __restrict__ src,
                                                     const int* __restrict__ dst) {
    int e = blockIdx.x * blockDim.x + threadIdx.x;
    if (e < NEDGES) {
        atomicAdd(&g_deg_out[src[e]], 1.0f);
        atomicAdd(&g_deg_in[dst[e]], 1.0f);
    }
}

// ---------------- norms ----------------
__global__ __launch_bounds__(256) void norm_kernel() {
    int i = blockIdx.x * blockDim.x + threadIdx.x;
    if (i < NNODES) {
        g_norm_src[i] = rsqrtf(fmaxf(g_deg_out[i], 1.0f));
        g_norm_dst[i] = rsqrtf(fmaxf(g_deg_in[i], 1.0f));
    }
}

// ---------------- scan stage A ----------------
__global__ __launch_bounds__(256) void scan_a_kernel() {
    __shared__ int wsum[8];
    int t = threadIdx.x, lane = t & 31, wid = t >> 5;
    int i = blockIdx.x * 256 + t;
    int v = (i < NNODES) ? (int)g_deg_in[i] : 0;
    int x = v;
#pragma unroll
    for (int o = 1; o < 32; o <<= 1) { int y = __shfl_up_sync(~0u, x, o); if (lane >= o) x += y; }
    if (lane == 31) wsum[wid] = x;
    __syncthreads();
    if (wid == 0 && lane < 8) {
        int w = wsum[lane];
#pragma unroll
        for (int o = 1; o < 8; o <<= 1) { int y = __shfl_up_sync(0xffu, w, o); if (lane >= o) w += y; }
        wsum[lane] = w;
    }
    __syncthreads();
    int incl = x + (wid ? wsum[wid - 1] : 0);
    if (i < NNODES) g_off[i] = incl - v;
    if (t == 255) g_bsum[blockIdx.x] = incl;
}

// ---------------- scan stage B ----------------
__global__ __launch_bounds__(256) void scan_b_kernel() {
    __shared__ int wsum[8];
    int t = threadIdx.x, lane = t & 31, wid = t >> 5;
    int v = (t < SCAN_B) ? g_bsum[t] : 0;
    int x = v;
#pragma unroll
    for (int o = 1; o < 32; o <<= 1) { int y = __shfl_up_sync(~0u, x, o); if (lane >= o) x += y; }
    if (lane == 31) wsum[wid] = x;
    __syncthreads();
    if (wid == 0 && lane < 8) {
        int w = wsum[lane];
#pragma unroll
        for (int o = 1; o < 8; o <<= 1) { int y = __shfl_up_sync(0xffu, w, o); if (lane >= o) w += y; }
        wsum[lane] = w;
    }
    __syncthreads();
    int incl = x + (wid ? wsum[wid - 1] : 0);
    if (t < SCAN_B) g_boff[t] = incl - v;
    if (t == SCAN_B - 1) g_off[NNODES] = incl;
}

// ---------------- scan stage C ----------------
__global__ __launch_bounds__(256) void scan_c_kernel() {
    int i = blockIdx.x * 256 + threadIdx.x;
    if (i < NNODES && blockIdx.x > 0) g_off[i] += g_boff[blockIdx.x];
}

// ---------------- CSR fill ----------------
__global__ __launch_bounds__(256) void fill_kernel(const int* __restrict__ src,
                                                   const int* __restrict__ dst) {
    int e = blockIdx.x * blockDim.x + threadIdx.x;
    if (e < NEDGES) {
        int d = dst[e];
        int p = atomicAdd(&g_cursor[d], 1);
        g_eidx[g_off[d] + p] = src[e];
    }
}

// ---------------- layer 0: gather scalar + dense, fused; writes fp16 ha -------
__global__ __launch_bounds__(256) void gather0_dense_kernel(const float* __restrict__ W0,
                                                            const float* __restrict__ b0) {
    int node = (blockIdx.x * blockDim.x + threadIdx.x) >> 5;
    int lane = threadIdx.x & 31;
    if (node >= NNODES) return;
    int beg = g_off[node], end = g_off[node + 1];
    float a = 0.f;
    for (int j = beg + lane; j < end; j += 32) {
        int s = g_eidx[j];
        a += g_deg_in[s] * g_norm_src[s];
    }
#pragma unroll
    for (int o = 16; o; o >>= 1) a += __shfl_xor_sync(~0u, a, o);
    a *= g_norm_dst[node];
    float ns = g_norm_src[node];
    float4 w = __ldg(&((const float4*)W0)[lane]);
    float4 b = __ldg(&((const float4*)b0)[lane]);
    uint2 u = pack_h4(fmaxf(a * w.x + b.x, 0.f) * ns,
                      fmaxf(a * w.y + b.y, 0.f) * ns,
                      fmaxf(a * w.z + b.z, 0.f) * ns,
                      fmaxf(a * w.w + b.w, 0.f) * ns);
    ((uint2*)(g_ha16))[(size_t)node * 32 + lane] = u;
}

// ---------------- fused gather + GEMM (cp.async W staging overlaps gather) ----
// PHASE 0: gather g_ha16 -> A; out = relu(A*nd @ W1 + b)*ns -> g_hb16
// PHASE 1: gather g_hb16 -> A; out = relu(A*nd @ W2 + b)    -> g_ha (fp32)
// dyn smem (words): As 64*68 | Wh 128*68 | Wl 128*68
template <int PHASE>
__global__ __launch_bounds__(256, 2) void fused_gemm_kernel(const float* __restrict__ bias) {
    const uint2* __restrict__ hsrc = (const uint2*)(PHASE == 0 ? g_ha16 : g_hb16);
    extern __shared__ uint32_t smw[];
    uint32_t* asw = smw;                 // 64*68 = 4352 words
    uint32_t* whw = smw + 4352;          // 128*68 = 8704 words
    uint32_t* wlw = smw + 13056;

    int t = threadIdx.x;
    int w = t >> 5, lane = t & 31;
    int gid = lane >> 2, tig = lane & 3;
    int m_base = (w >> 1) * 16;
    int n_base = (w & 1) * 64;
    int row0 = blockIdx.x * 64;

    // ---- async-stage pre-split W: DMA runs during the gather phase ----
    // 2048 16B chunks per array; chunk idx: n = idx>>4, kc = idx&15.
    {
        const char* whg = (const char*)(g_Wh + (size_t)PHASE * HID * HID);
        const char* wlg = (const char*)(g_Wl + (size_t)PHASE * HID * HID);
        uint32_t whs = (uint32_t)__cvta_generic_to_shared(whw);
        uint32_t wls = (uint32_t)__cvta_generic_to_shared(wlw);
#pragma unroll
        for (int i = 0; i < 8; i++) {
            int idx = t + i * 256;               // 0..2047
            int n = idx >> 4, kc = idx & 15;
            uint32_t dst = (uint32_t)(n * 68 + kc * 4) * 4u;
            cp_async16(whs + dst, whg + idx * 16);
            cp_async16(wls + dst, wlg + idx * 16);
        }
        asm volatile("cp.async.commit_group;" ::: "memory");
    }

    // ---- gather: warp w fills rows w*8 .. w*8+7 of As; prefetched offsets ----
    int offv = 0;
    {
        int nidx = row0 + w * 8 + lane;
        if (lane < 9) offv = g_off[nidx <= NNODES ? nidx : NNODES];
    }
    int pb[8], pe[8], pidx[8];
#pragma unroll
    for (int i = 0; i < 8; i++) {
        pb[i] = __shfl_sync(~0u, offv, i);
        pe[i] = __shfl_sync(~0u, offv, i + 1);
        pidx[i] = (pb[i] + lane < pe[i]) ? __ldg(&g_eidx[pb[i] + lane]) : 0;
    }
#pragma unroll
    for (int i = 0; i < 8; i++) {
        int r = w * 8 + i;
        int node = row0 + r;
        float4 a0 = make_float4(0.f, 0.f, 0.f, 0.f);
        float4 a1 = make_float4(0.f, 0.f, 0.f, 0.f);
        if (node < NNODES) {
            int beg = pb[i], end = pe[i];
            int myidx = pidx[i];
            for (int j = beg; j < end; j += 32) {
                if (j != beg) {
                    int n = end - j;
                    myidx = (lane < n) ? __ldg(&g_eidx[j + lane]) : 0;
                }
                int rem = end - j;
                int cnt = rem < 32 ? rem : 32;
                int k = 0;
                for (; k + 1 < cnt; k += 2) {
                    int s0 = __shfl_sync(~0u, myidx, k);
                    int s1 = __shfl_sync(~0u, myidx, k + 1);
                    uint2 u0 = __ldg(&hsrc[(size_t)s0 * 32 + lane]);
                    uint2 u1 = __ldg(&hsrc[(size_t)s1 * 32 + lane]);
                    float2 f00 = __half22float2(*(__half2*)&u0.x);
                    float2 f01 = __half22float2(*(__half2*)&u0.y);
                    float2 f10 = __half22float2(*(__half2*)&u1.x);
                    float2 f11 = __half22float2(*(__half2*)&u1.y);
                    a0.x += f00.x; a0.y += f00.y; a0.z += f01.x; a0.w += f01.y;
                    a1.x += f10.x; a1.y += f10.y; a1.z += f11.x; a1.w += f11.y;
                }
                if (k < cnt) {
                    int s0 = __shfl_sync(~0u, myidx, k);
                    uint2 u0 = __ldg(&hsrc[(size_t)s0 * 32 + lane]);
                    float2 f00 = __half22float2(*(__half2*)&u0.x);
                    float2 f01 = __half22float2(*(__half2*)&u0.y);
                    a0.x += f00.x; a0.y += f00.y; a0.z += f01.x; a0.w += f01.y;
                }
            }
            float nd = g_norm_dst[node];
            a0.x = (a0.x + a1.x) * nd;
            a0.y = (a0.y + a1.y) * nd;
            a0.z = (a0.z + a1.z) * nd;
            a0.w = (a0.w + a1.w) * nd;
        }
        uint2 u = pack_h4(a0.x, a0.y, a0.z, a0.w);
        *(uint2*)&asw[r * 68 + lane * 2] = u;
    }
    asm volatile("cp.async.wait_group 0;" ::: "memory");
    __syncthreads();

    // ---- MMA mainloop: no barriers ----
    float d[8][4];
#pragma unroll
    for (int nt = 0; nt < 8; nt++)
#pragma unroll
        for (int i = 0; i < 4; i++) d[nt][i] = 0.f;

#pragma unroll
    for (int kb = 0; kb < 8; kb++) {       // k16 steps
        uint32_t a[4];
        int aw0 = (m_base + gid) * 68 + kb * 8 + tig;
        int aw1 = (m_base + gid + 8) * 68 + kb * 8 + tig;
        a[0] = asw[aw0];
        a[1] = asw[aw1];
        a[2] = asw[aw0 + 4];
        a[3] = asw[aw1 + 4];
#pragma unroll
        for (int nt = 0; nt < 8; nt++) {
            int n = n_base + nt * 8 + gid;
            int bw = n * 68 + kb * 8 + tig;
            uint32_t bh0 = whw[bw];
            uint32_t bh1 = whw[bw + 4];
            uint32_t bl0 = wlw[bw];
            uint32_t bl1 = wlw[bw + 4];
            mma_f16(d[nt], a, bh0, bh1);
            mma_f16(d[nt], a, bl0, bl1);
        }
    }

    // ---- epilogue (bias hoisted) ----
#pragma unroll
    for (int nt = 0; nt < 8; nt++) {
        int c0 = n_base + nt * 8 + 2 * tig;
        float b0v = __ldg(&bias[c0]);
        float b1v = __ldg(&bias[c0 + 1]);
#pragma unroll
        for (int half_r = 0; half_r < 2; half_r++) {
            int row = row0 + m_base + gid + half_r * 8;
            if (row < NNODES) {
                float v0 = fmaxf(d[nt][half_r * 2 + 0] + b0v, 0.0f);
                float v1 = fmaxf(d[nt][half_r * 2 + 1] + b1v, 0.0f);
                if (PHASE == 0) {
                    float ns = g_norm_src[row];
                    __half2 p = __floats2half2_rn(v0 * ns, v1 * ns);
                    *(uint32_t*)&g_hb16[(size_t)row * HID + c0] = *(uint32_t*)&p;
                } else {
                    g_ha[(size_t)row * HID + c0] = v0;
                    g_ha[(size_t)row * HID + c0 + 1] = v1;
                }
            }
        }
    }
}

// ---------------- pooling: segmented sum, graph_ids sorted, float4 lanes ------
__global__ __launch_bounds__(128) void pool_kernel(const int* __restrict__ gid) {
    const float4* __restrict__ h4 = (const float4*)g_ha;
    int q = threadIdx.x & 31;
    int sub = threadIdx.x >> 5;
    int n0 = blockIdx.x * 64 + sub * 16;
    int nend = n0 + 16;
    if (nend > NNODES) nend = NNODES;
    if (n0 >= NNODES) return;
    float4 acc = make_float4(0.f, 0.f, 0.f, 0.f);
    int cacc = 0;
    int cur = __ldg(&gid[n0]);
    for (int n = n0; n < nend; n++) {
        int g = __ldg(&gid[n]);
        if (g != cur) {
            red_add_v4(&g_hg[cur * HID + q * 4], acc);
            if (q == 0) atomicAdd(&g_cnt[cur], (float)cacc);
            acc = make_float4(0.f, 0.f, 0.f, 0.f); cacc = 0; cur = g;
        }
        float4 v = h4[(size_t)n * 32 + q];
        acc.x += v.x; acc.y += v.y; acc.z += v.z; acc.w += v.w;
        cacc++;
    }
    red_add_v4(&g_hg[cur * HID + q * 4], acc);
    if (q == 0) atomicAdd(&g_cnt[cur], (float)cacc);
}

// ---------------- classifier: out = (hg/cnt) @ Wc + bc ----------------
__global__ __launch_bounds__(256) void cls_kernel(const float* __restrict__ Wc,
                                                  const float* __restrict__ bc,
                                                  float* __restrict__ out) {
    int g = blockIdx.x * (blockDim.x >> 5) + (threadIdx.x >> 5);
    int lane = threadIdx.x & 31;
    if (g >= NGRAPHS) return;
    float inv = 1.0f / fmaxf(g_cnt[g], 1.0f);
    float x[4];
#pragma unroll
    for (int j = 0; j < 4; j++) x[j] = g_hg[g * HID + lane + j * 32] * inv;
#pragma unroll
    for (int cls = 0; cls < NCLS; cls++) {
        float p = 0.f;
#pragma unroll
        for (int j = 0; j < 4; j++) p += x[j] * __ldg(&Wc[(lane + j * 32) * NCLS + cls]);
#pragma unroll
        for (int o = 16; o; o >>= 1) p += __shfl_xor_sync(0xffffffffu, p, o);
        if (lane == 0) out[g * NCLS + cls] = p + __ldg(&bc[cls]);
    }
}

// ---------------- launch ----------------
extern "C" void kernel_launch(void* const* d_in, const int* in_sizes, int n_in,
                              void* d_out, int out_size) {
    const float* W0 = (const float*)d_in[0];
    const float* b0 = (const float*)d_in[1];
    const float* W1 = (const float*)d_in[2];
    const float* b1 = (const float*)d_in[3];
    const float* W2 = (const float*)d_in[4];
    const float* b2 = (const float*)d_in[5];
    const float* Wc = (const float*)d_in[6];
    const float* bc = (const float*)d_in[7];
    const int* src = (const int*)d_in[8];
    const int* dst = (const int*)d_in[9];
    const int* gid = (const int*)d_in[10];
    float* out = (float*)d_out;

    const int EB = (NEDGES + 255) / 256;
    const int NB = (NNODES + 255) / 256;       // == SCAN_B
    const int ZB = (NGRAPHS * HID + 255) / 256;
    const int WB = (NNODES * 32 + 255) / 256;
    const int GB = (NNODES + 63) / 64;         // 782 fused-GEMM blocks

    cudaFuncSetAttribute(fused_gemm_kernel<0>,
                         cudaFuncAttributeMaxDynamicSharedMemorySize, FUSED_SMEM);
    cudaFuncSetAttribute(fused_gemm_kernel<1>,
                         cudaFuncAttributeMaxDynamicSharedMemorySize, FUSED_SMEM);

    zero_kernel<<<ZB, 256>>>();
    degree_kernel<<<EB, 256>>>(src, dst);
    norm_kernel<<<NB, 256>>>();
    scan_a_kernel<<<SCAN_B, 256>>>();
    scan_b_kernel<<<1, 256>>>();
    scan_c_kernel<<<SCAN_B, 256>>>();
    fill_kernel<<<EB, 256>>>(src, dst);
    wsplit_kernel<<<128, 256>>>(W1, W2);

    gather0_dense_kernel<<<WB, 256>>>(W0, b0);

    fused_gemm_kernel<0><<<GB, 256, FUSED_SMEM>>>(b1);
    fused_gemm_kernel<1><<<GB, 256, FUSED_SMEM>>>(b2);

    pool_kernel<<<GB, 128>>>(gid);
    cls_kernel<<<(NGRAPHS + 7) / 8, 256>>>(Wc, bc, out);
}

// round 16
// speedup vs baseline: 1.5613x; 1.2301x over previous
#include <cuda_runtime.h>
#include <cuda_fp16.h>
#include <cstdint>

#define NNODES 50000
#define NEDGES 800000
#define NGRAPHS 512
#define HID 128
#define NCLS 10
#define SCAN_B ((NNODES + 255) / 256)   // 196 scan blocks
#define FUSED_SMEM 87040                // (64*68 + 2*128*68) words * 4B

// ---------------- scratch (device globals; no allocs allowed) ----------------
__device__ float g_deg_in[NNODES];
__device__ float g_deg_out[NNODES];
__device__ float g_norm_src[NNODES];
__device__ float g_norm_dst[NNODES];
__device__ __half g_ha16[(size_t)NNODES * HID];   // fp16 gather input, layer 1
__device__ __half g_hb16[(size_t)NNODES * HID];   // fp16 gather input, layer 2
__device__ float g_ha[(size_t)NNODES * HID];      // fp32 final h (pool input)
__device__ float g_hg[NGRAPHS * HID];
__device__ float g_cnt[NGRAPHS];
__device__ __half g_Wh[2 * HID * HID];            // pre-split W hi, transposed [n][k]
__device__ __half g_Wl[2 * HID * HID];            // pre-split W lo residual
// CSR by destination
__device__ int g_off[NNODES + 1];
__device__ int g_cursor[NNODES];
__device__ int g_eidx[NEDGES];
__device__ int g_bsum[SCAN_B];
__device__ int g_boff[SCAN_B];

__device__ __forceinline__ void red_add_v4(float* addr, float4 v) {
    asm volatile("red.global.add.v4.f32 [%0], {%1,%2,%3,%4};"
                 :: "l"(addr), "f"(v.x), "f"(v.y), "f"(v.z), "f"(v.w) : "memory");
}

// fp16 MMA m16n8k16, fp32 accum
__device__ __forceinline__ void mma_f16(float d[4], const uint32_t a[4],
                                        uint32_t b0, uint32_t b1) {
    asm volatile("mma.sync.aligned.m16n8k16.row.col.f32.f16.f16.f32 "
                 "{%0,%1,%2,%3}, {%4,%5,%6,%7}, {%8,%9}, {%0,%1,%2,%3};"
                 : "+f"(d[0]), "+f"(d[1]), "+f"(d[2]), "+f"(d[3])
                 : "r"(a[0]), "r"(a[1]), "r"(a[2]), "r"(a[3]), "r"(b0), "r"(b1));
}

__device__ __forceinline__ uint2 pack_h4(float x, float y, float z, float w) {
    __half2 p0 = __floats2half2_rn(x, y);
    __half2 p1 = __floats2half2_rn(z, w);
    uint2 u;
    u.x = *(uint32_t*)&p0;
    u.y = *(uint32_t*)&p1;
    return u;
}

// 16B async copy global -> shared (bypasses registers)
__device__ __forceinline__ void cp_async16(uint32_t smem_addr, const void* gptr) {
    asm volatile("cp.async.cg.shared.global [%0], [%1], 16;"
                 :: "r"(smem_addr), "l"(gptr) : "memory");
}

// ---------------- zero all accumulated state ----------------
__global__ __launch_bounds__(256) void zero_kernel() {
    int i = blockIdx.x * blockDim.x + threadIdx.x;     // 0..65535
    if (i < NNODES) { g_deg_in[i] = 0.f; g_deg_out[i] = 0.f; g_cursor[i] = 0; }
    if (i < NGRAPHS * HID) g_hg[i] = 0.f;
    if (i < NGRAPHS) g_cnt[i] = 0.f;
}

// ---------------- W pre-split: hi/lo fp16, transposed [n][k] ------------------
__global__ __launch_bounds__(256) void wsplit_kernel(const float* __restrict__ W1,
                                                     const float* __restrict__ W2) {
    int i = blockIdx.x * blockDim.x + threadIdx.x;   // 0..32767
    int w = i >> 14, idx = i & 16383;
    int k = idx >> 7, n = idx & 127;
    const float* W = w ? W2 : W1;
    float v = W[k * HID + n];
    __half h = __float2half(v);
    g_Wh[w * HID * HID + n * HID + k] = h;
    g_Wl[w * HID * HID + n * HID + k] = __float2half(v - __half2float(h));
}

// ---------------- degree histograms ----------------
__global__ __launch_bounds__(256) void degree_kernel(const int* __restrict__ src,
                                                     const int* __restrict__ dst) {
    int e = blockIdx.x * blockDim.x + threadIdx.x;
    if (e < NEDGES) {
        atomicAdd(&g_deg_out[src[e]], 1.0f);
        atomicAdd(&g_deg_in[dst[e]], 1.0f);
    }
}

// ---------------- norms ----------------
__global__ __launch_bounds__(256) void norm_kernel() {
    int i = blockIdx.x * blockDim.x + threadIdx.x;
    if (i < NNODES) {
        g_norm_src[i] = rsqrtf(fmaxf(g_deg_out[i], 1.0f));
        g_norm_dst[i] = rsqrtf(fmaxf(g_deg_in[i], 1.0f));
    }
}

// ---------------- scan stage A ----------------
__global__ __launch_bounds__(256) void scan_a_kernel() {
    __shared__ int wsum[8];
    int t = threadIdx.x, lane = t & 31, wid = t >> 5;
    int i = blockIdx.x * 256 + t;
    int v = (i < NNODES) ? (int)g_deg_in[i] : 0;
    int x = v;
#pragma unroll
    for (int o = 1; o < 32; o <<= 1) { int y = __shfl_up_sync(~0u, x, o); if (lane >= o) x += y; }
    if (lane == 31) wsum[wid] = x;
    __syncthreads();
    if (wid == 0 && lane < 8) {
        int w = wsum[lane];
#pragma unroll
        for (int o = 1; o < 8; o <<= 1) { int y = __shfl_up_sync(0xffu, w, o); if (lane >= o) w += y; }
        wsum[lane] = w;
    }
    __syncthreads();
    int incl = x + (wid ? wsum[wid - 1] : 0);
    if (i < NNODES) g_off[i] = incl - v;
    if (t == 255) g_bsum[blockIdx.x] = incl;
}

// ---------------- scan stage B ----------------
__global__ __launch_bounds__(256) void scan_b_kernel() {
    __shared__ int wsum[8];
    int t = threadIdx.x, lane = t & 31, wid = t >> 5;
    int v = (t < SCAN_B) ? g_bsum[t] : 0;
    int x = v;
#pragma unroll
    for (int o = 1; o < 32; o <<= 1) { int y = __shfl_up_sync(~0u, x, o); if (lane >= o) x += y; }
    if (lane == 31) wsum[wid] = x;
    __syncthreads();
    if (wid == 0 && lane < 8) {
        int w = wsum[lane];
#pragma unroll
        for (int o = 1; o < 8; o <<= 1) { int y = __shfl_up_sync(0xffu, w, o); if (lane >= o) w += y; }
        wsum[lane] = w;
    }
    __syncthreads();
    int incl = x + (wid ? wsum[wid - 1] : 0);
    if (t < SCAN_B) g_boff[t] = incl - v;
    if (t == SCAN_B - 1) g_off[NNODES] = incl;
}

// ---------------- scan stage C ----------------
__global__ __launch_bounds__(256) void scan_c_kernel() {
    int i = blockIdx.x * 256 + threadIdx.x;
    if (i < NNODES && blockIdx.x > 0) g_off[i] += g_boff[blockIdx.x];
}

// ---------------- CSR fill ----------------
__global__ __launch_bounds__(256) void fill_kernel(const int* __restrict__ src,
                                                   const int* __restrict__ dst) {
    int e = blockIdx.x * blockDim.x + threadIdx.x;
    if (e < NEDGES) {
        int d = dst[e];
        int p = atomicAdd(&g_cursor[d], 1);
        g_eidx[g_off[d] + p] = src[e];
    }
}

// ---------------- layer 0: gather scalar + dense, fused; writes fp16 ha -------
__global__ __launch_bounds__(256) void gather0_dense_kernel(const float* __restrict__ W0,
                                                            const float* __restrict__ b0) {
    int node = (blockIdx.x * blockDim.x + threadIdx.x) >> 5;
    int lane = threadIdx.x & 31;
    if (node >= NNODES) return;
    int beg = g_off[node], end = g_off[node + 1];
    float a = 0.f;
    for (int j = beg + lane; j < end; j += 32) {
        int s = g_eidx[j];
        a += g_deg_in[s] * g_norm_src[s];
    }
#pragma unroll
    for (int o = 16; o; o >>= 1) a += __shfl_xor_sync(~0u, a, o);
    a *= g_norm_dst[node];
    float ns = g_norm_src[node];
    float4 w = __ldg(&((const float4*)W0)[lane]);
    float4 b = __ldg(&((const float4*)b0)[lane]);
    uint2 u = pack_h4(fmaxf(a * w.x + b.x, 0.f) * ns,
                      fmaxf(a * w.y + b.y, 0.f) * ns,
                      fmaxf(a * w.z + b.z, 0.f) * ns,
                      fmaxf(a * w.w + b.w, 0.f) * ns);
    ((uint2*)(g_ha16))[(size_t)node * 32 + lane] = u;
}

// ---------------- fused gather + GEMM: 512 threads, 16 warps, 4 nodes/warp ----
// PHASE 0: gather g_ha16 -> A; out = relu(A*nd @ W1 + b)*ns -> g_hb16
// PHASE 1: gather g_hb16 -> A; out = relu(A*nd @ W2 + b)    -> g_ha (fp32)
// dyn smem (words): As 64*68 | Wh 128*68 | Wl 128*68
template <int PHASE>
__global__ __launch_bounds__(512, 2) void fused_gemm_kernel(const float* __restrict__ bias) {
    const uint2* __restrict__ hsrc = (const uint2*)(PHASE == 0 ? g_ha16 : g_hb16);
    extern __shared__ uint32_t smw[];
    uint32_t* asw = smw;                 // 64*68 = 4352 words
    uint32_t* whw = smw + 4352;          // 128*68 = 8704 words
    uint32_t* wlw = smw + 13056;

    int t = threadIdx.x;
    int w = t >> 5, lane = t & 31;       // 16 warps
    int gid = lane >> 2, tig = lane & 3;
    int m_base = (w >> 2) * 16;          // 0,16,32,48
    int n_base = (w & 3) * 32;           // 0,32,64,96
    int row0 = blockIdx.x * 64;

    // ---- async-stage pre-split W: DMA runs during the gather phase ----
    {
        const char* whg = (const char*)(g_Wh + (size_t)PHASE * HID * HID);
        const char* wlg = (const char*)(g_Wl + (size_t)PHASE * HID * HID);
        uint32_t whs = (uint32_t)__cvta_generic_to_shared(whw);
        uint32_t wls = (uint32_t)__cvta_generic_to_shared(wlw);
#pragma unroll
        for (int i = 0; i < 4; i++) {
            int idx = t + i * 512;               // 0..2047
            int n = idx >> 4, kc = idx & 15;
            uint32_t dst = (uint32_t)(n * 68 + kc * 4) * 4u;
            cp_async16(whs + dst, whg + idx * 16);
            cp_async16(wls + dst, wlg + idx * 16);
        }
        asm volatile("cp.async.commit_group;" ::: "memory");
    }

    // ---- gather: warp w fills rows w*4 .. w*4+3 of As; prefetched offsets ----
    int offv = 0;
    {
        int nidx = row0 + w * 4 + lane;
        if (lane < 5) offv = g_off[nidx <= NNODES ? nidx : NNODES];
    }
    int pb[4], pe[4], pidx[4];
#pragma unroll
    for (int i = 0; i < 4; i++) {
        pb[i] = __shfl_sync(~0u, offv, i);
        pe[i] = __shfl_sync(~0u, offv, i + 1);
        pidx[i] = (pb[i] + lane < pe[i]) ? __ldg(&g_eidx[pb[i] + lane]) : 0;
    }
#pragma unroll
    for (int i = 0; i < 4; i++) {
        int r = w * 4 + i;
        int node = row0 + r;
        float4 a0 = make_float4(0.f, 0.f, 0.f, 0.f);
        float4 a1 = make_float4(0.f, 0.f, 0.f, 0.f);
        if (node < NNODES) {
            int beg = pb[i], end = pe[i];
            int myidx = pidx[i];
            for (int j = beg; j < end; j += 32) {
                if (j != beg) {
                    int n = end - j;
                    myidx = (lane < n) ? __ldg(&g_eidx[j + lane]) : 0;
                }
                int rem = end - j;
                int cnt = rem < 32 ? rem : 32;
                int k = 0;
                for (; k + 1 < cnt; k += 2) {
                    int s0 = __shfl_sync(~0u, myidx, k);
                    int s1 = __shfl_sync(~0u, myidx, k + 1);
                    uint2 u0 = __ldg(&hsrc[(size_t)s0 * 32 + lane]);
                    uint2 u1 = __ldg(&hsrc[(size_t)s1 * 32 + lane]);
                    float2 f00 = __half22float2(*(__half2*)&u0.x);
                    float2 f01 = __half22float2(*(__half2*)&u0.y);
                    float2 f10 = __half22float2(*(__half2*)&u1.x);
                    float2 f11 = __half22float2(*(__half2*)&u1.y);
                    a0.x += f00.x; a0.y += f00.y; a0.z += f01.x; a0.w += f01.y;
                    a1.x += f10.x; a1.y += f10.y; a1.z += f11.x; a1.w += f11.y;
                }
                if (k < cnt) {
                    int s0 = __shfl_sync(~0u, myidx, k);
                    uint2 u0 = __ldg(&hsrc[(size_t)s0 * 32 + lane]);
                    float2 f00 = __half22float2(*(__half2*)&u0.x);
                    float2 f01 = __half22float2(*(__half2*)&u0.y);
                    a0.x += f00.x; a0.y += f00.y; a0.z += f01.x; a0.w += f01.y;
                }
            }
            float nd = g_norm_dst[node];
            a0.x = (a0.x + a1.x) * nd;
            a0.y = (a0.y + a1.y) * nd;
            a0.z = (a0.z + a1.z) * nd;
            a0.w = (a0.w + a1.w) * nd;
        }
        uint2 u = pack_h4(a0.x, a0.y, a0.z, a0.w);
        *(uint2*)&asw[r * 68 + lane * 2] = u;
    }
    asm volatile("cp.async.wait_group 0;" ::: "memory");
    __syncthreads();

    // ---- MMA mainloop: m16 x n32 per warp, no barriers ----
    float d[4][4];
#pragma unroll
    for (int nt = 0; nt < 4; nt++)
#pragma unroll
        for (int i = 0; i < 4; i++) d[nt][i] = 0.f;

#pragma unroll
    for (int kb = 0; kb < 8; kb++) {       // k16 steps
        uint32_t a[4];
        int aw0 = (m_base + gid) * 68 + kb * 8 + tig;
        int aw1 = (m_base + gid + 8) * 68 + kb * 8 + tig;
        a[0] = asw[aw0];
        a[1] = asw[aw1];
        a[2] = asw[aw0 + 4];
        a[3] = asw[aw1 + 4];
#pragma unroll
        for (int nt = 0; nt < 4; nt++) {
            int n = n_base + nt * 8 + gid;
            int bw = n * 68 + kb * 8 + tig;
            uint32_t bh0 = whw[bw];
            uint32_t bh1 = whw[bw + 4];
            uint32_t bl0 = wlw[bw];
            uint32_t bl1 = wlw[bw + 4];
            mma_f16(d[nt], a, bh0, bh1);
            mma_f16(d[nt], a, bl0, bl1);
        }
    }

    // ---- epilogue (bias hoisted) ----
#pragma unroll
    for (int nt = 0; nt < 4; nt++) {
        int c0 = n_base + nt * 8 + 2 * tig;
        float b0v = __ldg(&bias[c0]);
        float b1v = __ldg(&bias[c0 + 1]);
#pragma unroll
        for (int half_r = 0; half_r < 2; half_r++) {
            int row = row0 + m_base + gid + half_r * 8;
            if (row < NNODES) {
                float v0 = fmaxf(d[nt][half_r * 2 + 0] + b0v, 0.0f);
                float v1 = fmaxf(d[nt][half_r * 2 + 1] + b1v, 0.0f);
                if (PHASE == 0) {
                    float ns = g_norm_src[row];
                    __half2 p = __floats2half2_rn(v0 * ns, v1 * ns);
                    *(uint32_t*)&g_hb16[(size_t)row * HID + c0] = *(uint32_t*)&p;
                } else {
                    g_ha[(size_t)row * HID + c0] = v0;
                    g_ha[(size_t)row * HID + c0 + 1] = v1;
                }
            }
        }
    }
}

// ---------------- pooling: segmented sum, graph_ids sorted, float4 lanes ------
__global__ __launch_bounds__(128) void pool_kernel(const int* __restrict__ gid) {
    const float4* __restrict__ h4 = (const float4*)g_ha;
    int q = threadIdx.x & 31;
    int sub = threadIdx.x >> 5;
    int n0 = blockIdx.x * 64 + sub * 16;
    int nend = n0 + 16;
    if (nend > NNODES) nend = NNODES;
    if (n0 >= NNODES) return;
    float4 acc = make_float4(0.f, 0.f, 0.f, 0.f);
    int cacc = 0;
    int cur = __ldg(&gid[n0]);
    for (int n = n0; n < nend; n++) {
        int g = __ldg(&gid[n]);
        if (g != cur) {
            red_add_v4(&g_hg[cur * HID + q * 4], acc);
            if (q == 0) atomicAdd(&g_cnt[cur], (float)cacc);
            acc = make_float4(0.f, 0.f, 0.f, 0.f); cacc = 0; cur = g;
        }
        float4 v = h4[(size_t)n * 32 + q];
        acc.x += v.x; acc.y += v.y; acc.z += v.z; acc.w += v.w;
        cacc++;
    }
    red_add_v4(&g_hg[cur * HID + q * 4], acc);
    if (q == 0) atomicAdd(&g_cnt[cur], (float)cacc);
}

// ---------------- classifier: out = (hg/cnt) @ Wc + bc ----------------
__global__ __launch_bounds__(256) void cls_kernel(const float* __restrict__ Wc,
                                                  const float* __restrict__ bc,
                                                  float* __restrict__ out) {
    int g = blockIdx.x * (blockDim.x >> 5) + (threadIdx.x >> 5);
    int lane = threadIdx.x & 31;
    if (g >= NGRAPHS) return;
    float inv = 1.0f / fmaxf(g_cnt[g], 1.0f);
    float x[4];
#pragma unroll
    for (int j = 0; j < 4; j++) x[j] = g_hg[g * HID + lane + j * 32] * inv;
#pragma unroll
    for (int cls = 0; cls < NCLS; cls++) {
        float p = 0.f;
#pragma unroll
        for (int j = 0; j < 4; j++) p += x[j] * __ldg(&Wc[(lane + j * 32) * NCLS + cls]);
#pragma unroll
        for (int o = 16; o; o >>= 1) p += __shfl_xor_sync(0xffffffffu, p, o);
        if (lane == 0) out[g * NCLS + cls] = p + __ldg(&bc[cls]);
    }
}

// ---------------- launch ----------------
extern "C" void kernel_launch(void* const* d_in, const int* in_sizes, int n_in,
                              void* d_out, int out_size) {
    const float* W0 = (const float*)d_in[0];
    const float* b0 = (const float*)d_in[1];
    const float* W1 = (const float*)d_in[2];
    const float* b1 = (const float*)d_in[3];
    const float* W2 = (const float*)d_in[4];
    const float* b2 = (const float*)d_in[5];
    const float* Wc = (const float*)d_in[6];
    const float* bc = (const float*)d_in[7];
    const int* src = (const int*)d_in[8];
    const int* dst = (const int*)d_in[9];
    const int* gid = (const int*)d_in[10];
    float* out = (float*)d_out;

    const int EB = (NEDGES + 255) / 256;
    const int NB = (NNODES + 255) / 256;       // == SCAN_B
    const int ZB = (NGRAPHS * HID + 255) / 256;
    const int WB = (NNODES * 32 + 255) / 256;
    const int GB = (NNODES + 63) / 64;         // 782 fused-GEMM blocks

    cudaFuncSetAttribute(fused_gemm_kernel<0>,
                         cudaFuncAttributeMaxDynamicSharedMemorySize, FUSED_SMEM);
    cudaFuncSetAttribute(fused_gemm_kernel<1>,
                         cudaFuncAttributeMaxDynamicSharedMemorySize, FUSED_SMEM);

    zero_kernel<<<ZB, 256>>>();
    degree_kernel<<<EB, 256>>>(src, dst);
    norm_kernel<<<NB, 256>>>();
    scan_a_kernel<<<SCAN_B, 256>>>();
    scan_b_kernel<<<1, 256>>>();
    scan_c_kernel<<<SCAN_B, 256>>>();
    fill_kernel<<<EB, 256>>>(src, dst);
    wsplit_kernel<<<128, 256>>>(W1, W2);

    gather0_dense_kernel<<<WB, 256>>>(W0, b0);

    fused_gemm_kernel<0><<<GB, 512, FUSED_SMEM>>>(b1);
    fused_gemm_kernel<1><<<GB, 512, FUSED_SMEM>>>(b2);

    pool_kernel<<<GB, 128>>>(gid);
    cls_kernel<<<(NGRAPHS + 7) / 8, 256>>>(Wc, bc, out);
}